// round 2
// baseline (speedup 1.0000x reference)
#include <cuda_runtime.h>

// GalerkinConv: out = ((x @ wbases) per-mode-mixed-by-W) @ bases^T
// B=16, C_IN=128, C_OUT=128, N=16384, MODES=128
#define BB 16
#define CI 128
#define CO 128
#define NPTS 16384
#define KM 128
#define SPLIT 16
#define CHUNK (NPTS / SPLIT)   // 1024

// Scratch (static device globals; no allocation)
__device__ float g_part[SPLIT * BB * CI * KM];  // 16.8 MB split-K partials (fits L2)
__device__ float g_xco [BB * CI * KM];          // 1 MB
__device__ float g_xhat[BB * CO * KM];          // 1 MB

// ---------------------------------------------------------------------------
// Kernel 1: x_co partials.  One block = (split s, batch b), full 128x128 tile,
// K-chunk of 1024 n-positions.  256 threads, 8x8 register micro-tile.
// ---------------------------------------------------------------------------
__global__ __launch_bounds__(256) void proj_kernel(const float* __restrict__ x,
                                                   const float* __restrict__ wb) {
    const int s  = blockIdx.x;
    const int b  = blockIdx.y;
    const int n0 = s * CHUNK;
    const int tid = threadIdx.x;
    const int tr = tid >> 4;    // c-group 0..15
    const int tc = tid & 15;    // mode-group 0..15

    __shared__ float As[16][132];      // As[kk][c] = x[b, c, nb+kk]
    __shared__ float Bs[16 * 128];     // Bs[kk*128+m] = wbases[nb+kk, m]

    float acc[8][8];
    #pragma unroll
    for (int i = 0; i < 8; i++)
        #pragma unroll
        for (int j = 0; j < 8; j++) acc[i][j] = 0.0f;

    const float* xb = x + (size_t)b * CI * NPTS;

    for (int t = 0; t < CHUNK / 16; t++) {
        const int nb = n0 + t * 16;
        // x tile: 128 c x 16 n, transpose into As[k][c]
        #pragma unroll
        for (int i = 0; i < 2; i++) {
            int e = tid * 2 + i;              // 0..511
            int c = e >> 2, q = e & 3;
            float4 v = *(const float4*)(xb + (size_t)c * NPTS + nb + q * 4);
            As[q * 4 + 0][c] = v.x;
            As[q * 4 + 1][c] = v.y;
            As[q * 4 + 2][c] = v.z;
            As[q * 4 + 3][c] = v.w;
        }
        // wbases tile: 16 rows x 128 = contiguous 2048 floats
        #pragma unroll
        for (int i = 0; i < 2; i++) {
            int e = tid + i * 256;            // float4 index 0..511
            *(float4*)(Bs + e * 4) =
                *(const float4*)(wb + (size_t)nb * KM + e * 4);
        }
        __syncthreads();

        #pragma unroll
        for (int kk = 0; kk < 16; kk++) {
            float a[8], bv[8];
            *(float4*)(a)     = *(const float4*)(&As[kk][tr * 8]);
            *(float4*)(a + 4) = *(const float4*)(&As[kk][tr * 8 + 4]);
            *(float4*)(bv)     = *(const float4*)(&Bs[kk * 128 + tc * 8]);
            *(float4*)(bv + 4) = *(const float4*)(&Bs[kk * 128 + tc * 8 + 4]);
            #pragma unroll
            for (int i = 0; i < 8; i++)
                #pragma unroll
                for (int j = 0; j < 8; j++)
                    acc[i][j] = fmaf(a[i], bv[j], acc[i][j]);
        }
        __syncthreads();
    }

    float* dst = g_part + ((size_t)s * BB + b) * CI * KM;
    #pragma unroll
    for (int i = 0; i < 8; i++) {
        int c = tr * 8 + i;
        #pragma unroll
        for (int j = 0; j < 8; j += 4)
            *(float4*)(dst + (size_t)c * KM + tc * 8 + j) = *(float4*)(&acc[i][j]);
    }
}

// ---------------------------------------------------------------------------
// Deterministic split-K reduction: g_xco = sum over SPLIT partials
// ---------------------------------------------------------------------------
__global__ __launch_bounds__(256) void reduce_kernel() {
    int idx = blockIdx.x * 256 + threadIdx.x;   // 262144 total
    float sum = 0.0f;
    #pragma unroll
    for (int p = 0; p < SPLIT; p++)
        sum += g_part[(size_t)p * (BB * CI * KM) + idx];
    g_xco[idx] = sum;
}

// ---------------------------------------------------------------------------
// Kernel 2: per-mode channel mix.  Block = (o, b), thread = mode k.
// All loads coalesced along k.
// ---------------------------------------------------------------------------
__global__ __launch_bounds__(128) void mix_kernel(const float* __restrict__ W) {
    const int o = blockIdx.x;
    const int b = blockIdx.y;
    const int k = threadIdx.x;
    const float* xc = g_xco + (size_t)b * CI * KM;
    const float* w  = W + (size_t)o * KM;      // W[i, o, k]
    float s = 0.0f;
    #pragma unroll 8
    for (int i = 0; i < CI; i++)
        s = fmaf(xc[(size_t)i * KM + k], w[(size_t)i * CO * KM + k], s);
    g_xhat[((size_t)b * CO + o) * KM + k] = s;
}

// ---------------------------------------------------------------------------
// Kernel 3: reconstruction.  Block = (x-tile 128, o-tile 64, b).
// 256 threads, 8(o) x 4(x) register micro-tile, K=128 loop.
// ---------------------------------------------------------------------------
__global__ __launch_bounds__(256) void recon_kernel(const float* __restrict__ bases,
                                                    float* __restrict__ out) {
    const int x0 = blockIdx.x * 128;
    const int o0 = blockIdx.y * 64;
    const int b  = blockIdx.z;
    const int tid = threadIdx.x;
    const int to = tid >> 5;     // 0..7
    const int tx = tid & 31;     // 0..31

    __shared__ float As[64 * 128];   // As[o][k] = x_hat[b, o0+o, k] (natural layout)
    __shared__ float Bs[16][132];    // Bs[kk][x] = bases[x0+x, kc+kk]

    // Load full A tile (contiguous 8192 floats)
    const float* xh = g_xhat + ((size_t)b * CO + o0) * KM;
    #pragma unroll
    for (int i = 0; i < 8; i++) {
        int e = tid + i * 256;       // float4 index 0..2047
        *(float4*)(As + e * 4) = *(const float4*)(xh + e * 4);
    }

    float acc[8][4];
    #pragma unroll
    for (int i = 0; i < 8; i++)
        #pragma unroll
        for (int j = 0; j < 4; j++) acc[i][j] = 0.0f;

    for (int c8 = 0; c8 < 8; c8++) {
        const int kc = c8 * 16;
        __syncthreads();   // Bs reuse WAR; first iter also orders nothing harmful
        // bases tile: 128 x-rows, 16 k each; transpose into Bs[k][x]
        #pragma unroll
        for (int i = 0; i < 2; i++) {
            int e = tid + i * 256;          // 0..511
            int xx = e >> 2, kq = e & 3;
            float4 v = *(const float4*)(bases + (size_t)(x0 + xx) * KM + kc + kq * 4);
            Bs[kq * 4 + 0][xx] = v.x;
            Bs[kq * 4 + 1][xx] = v.y;
            Bs[kq * 4 + 2][xx] = v.z;
            Bs[kq * 4 + 3][xx] = v.w;
        }
        __syncthreads();   // also covers As on the first iteration

        #pragma unroll
        for (int kk = 0; kk < 16; kk++) {
            float a[8];
            #pragma unroll
            for (int i = 0; i < 8; i++)
                a[i] = As[(to * 8 + i) * 128 + kc + kk];   // warp-broadcast
            float4 bv = *(const float4*)(&Bs[kk][tx * 4]);
            float bj[4] = {bv.x, bv.y, bv.z, bv.w};
            #pragma unroll
            for (int i = 0; i < 8; i++)
                #pragma unroll
                for (int j = 0; j < 4; j++)
                    acc[i][j] = fmaf(a[i], bj[j], acc[i][j]);
        }
    }

    float* ob = out + (size_t)b * CO * NPTS;
    #pragma unroll
    for (int i = 0; i < 8; i++) {
        int o = o0 + to * 8 + i;
        float4 v = make_float4(acc[i][0], acc[i][1], acc[i][2], acc[i][3]);
        *(float4*)(ob + (size_t)o * NPTS + x0 + tx * 4) = v;
    }
}

// ---------------------------------------------------------------------------
extern "C" void kernel_launch(void* const* d_in, const int* in_sizes, int n_in,
                              void* d_out, int out_size) {
    const float* x  = (const float*)d_in[0];   // [16,128,16384]
    const float* wb = (const float*)d_in[1];   // wbases [16384,128]
    const float* ba = (const float*)d_in[2];   // bases  [16384,128]
    const float* W  = (const float*)d_in[3];   // [128,128,128]
    float* out = (float*)d_out;                // [16,128,16384]

    proj_kernel<<<dim3(SPLIT, BB), 256>>>(x, wb);
    reduce_kernel<<<(BB * CI * KM) / 256, 256>>>();
    mix_kernel<<<dim3(CO, BB), 128>>>(W);
    recon_kernel<<<dim3(NPTS / 128, CO / 64, BB), 256>>>(ba, out);
}

// round 6
// speedup vs baseline: 1.2865x; 1.2865x over previous
#include <cuda_runtime.h>
#include <cuda_bf16.h>
#include <cstdint>

// GalerkinConv via mma.sync bf16 3-term split GEMMs (sm_103 baseline ISA)
// B=16, C_IN=128, C_OUT=128, N=16384, MODES=128
#define BB 16
#define CI 128
#define CO 128
#define NPTS 16384
#define KM 128
#define NSPLIT 32
#define KCH (NPTS / NSPLIT)   // 512 n per GEMM1 CTA
#define KBLK 64               // n per inner K-block

// ---------------- scratch (static device globals; no allocation) ----------
__device__ float         g_part[NSPLIT * BB * CI * KM];   // 33.5 MB split-K partials
__device__ float         g_xco [BB * CI * KM];
__device__ __nv_bfloat16 g_xhat_hi[BB * CO * KM];
__device__ __nv_bfloat16 g_xhat_lo[BB * CO * KM];
__device__ __nv_bfloat16 g_wbT_hi[KM * NPTS];             // wbases^T, [mode][n]
__device__ __nv_bfloat16 g_wbT_lo[KM * NPTS];
__device__ __nv_bfloat16 g_ba_hi[NPTS * KM];              // bases, [n][k]
__device__ __nv_bfloat16 g_ba_lo[NPTS * KM];

// ---------------- helpers --------------------------------------------------
__device__ __forceinline__ uint32_t smem_u32(const void* p) {
    uint32_t a;
    asm("{ .reg .u64 t; cvta.to.shared.u64 t, %1; cvt.u32.u64 %0, t; }"
        : "=r"(a) : "l"(p));
    return a;
}

// swizzles: XOR bits[4:6] with row-id bits so 8 consecutive rows hit distinct banks
#define SWZ128(o) ((o) ^ (((o) >> 3) & 0x70))   // 128B rows
#define SWZ256(o) ((o) ^ (((o) >> 4) & 0x70))   // 256B rows

#define LDSM_X4(r0, r1, r2, r3, a) \
    asm volatile("ldmatrix.sync.aligned.m8n8.x4.shared.b16 {%0,%1,%2,%3}, [%4];" \
                 : "=r"(r0), "=r"(r1), "=r"(r2), "=r"(r3) : "r"(a))
#define LDSM_X2(r0, r1, a) \
    asm volatile("ldmatrix.sync.aligned.m8n8.x2.shared.b16 {%0,%1}, [%2];" \
                 : "=r"(r0), "=r"(r1) : "r"(a))

__device__ __forceinline__ void mma16816(float* d, const uint32_t* a, const uint32_t* b) {
    asm volatile(
        "mma.sync.aligned.m16n8k16.row.col.f32.bf16.bf16.f32 "
        "{%0,%1,%2,%3}, {%4,%5,%6,%7}, {%8,%9}, {%0,%1,%2,%3};"
        : "+f"(d[0]), "+f"(d[1]), "+f"(d[2]), "+f"(d[3])
        : "r"(a[0]), "r"(a[1]), "r"(a[2]), "r"(a[3]), "r"(b[0]), "r"(b[1]));
}

__device__ __forceinline__ void split2(float v, __nv_bfloat16& h, __nv_bfloat16& l) {
    h = __float2bfloat16(v);
    l = __float2bfloat16(v - __bfloat162float(h));
}
__device__ __forceinline__ uint32_t pack2(__nv_bfloat16 a, __nv_bfloat16 b) {
    return (uint32_t)__bfloat16_as_ushort(a) | ((uint32_t)__bfloat16_as_ushort(b) << 16);
}

// ---------------------------------------------------------------------------
// prep: wbases [n,k] -> wbT hi/lo [k][n]  (transpose + bf16 split)
// ---------------------------------------------------------------------------
__global__ void prep_wb(const float* __restrict__ wb) {
    __shared__ float t[32][33];
    const int n0 = blockIdx.x * 32, k0 = blockIdx.y * 32;
    const int tx = threadIdx.x, ty = threadIdx.y;   // (32, 8)
    #pragma unroll
    for (int i = 0; i < 4; i++)
        t[ty + i * 8][tx] = wb[(size_t)(n0 + ty + i * 8) * KM + k0 + tx];
    __syncthreads();
    #pragma unroll
    for (int i = 0; i < 4; i++) {
        float v = t[tx][ty + i * 8];
        __nv_bfloat16 h, l; split2(v, h, l);
        size_t idx = (size_t)(k0 + ty + i * 8) * NPTS + n0 + tx;
        g_wbT_hi[idx] = h;
        g_wbT_lo[idx] = l;
    }
}

__global__ void prep_ba(const float* __restrict__ ba) {
    int i = blockIdx.x * 256 + threadIdx.x;
    float v = ba[i];
    __nv_bfloat16 h, l; split2(v, h, l);
    g_ba_hi[i] = h;
    g_ba_lo[i] = l;
}

// ---------------------------------------------------------------------------
// GEMM1: partial[s][b] = x[b,:,s*512:(s+1)*512] @ wbases-chunk
//   M=128 (c), N=128 (modes), K=512 in blocks of 64.
//   8 warps as 2(M)x4(N): warp tile 64x32.
// ---------------------------------------------------------------------------
#define G1_SMEM (4 * 16384)
__global__ __launch_bounds__(256) void gemm1_kernel(const float* __restrict__ x) {
    extern __shared__ __align__(128) char smem[];
    const uint32_t sb = smem_u32(smem);
    const int s = blockIdx.x, b = blockIdx.y;
    const int tid = threadIdx.x, wid = tid >> 5, lane = tid & 31;
    const int AH = 0, AL = 16384, BH = 32768, BL = 49152;
    const int m0 = (wid >> 2) * 64, n0 = (wid & 3) * 32;

    float acc[4][4][4];
    #pragma unroll
    for (int mi = 0; mi < 4; mi++)
        #pragma unroll
        for (int ni = 0; ni < 4; ni++)
            #pragma unroll
            for (int j = 0; j < 4; j++) acc[mi][ni][j] = 0.0f;

    const float* xb = x + (size_t)b * CI * NPTS + (size_t)s * KCH;
    const __nv_bfloat16* wh = g_wbT_hi + (size_t)s * KCH;
    const __nv_bfloat16* wl = g_wbT_lo + (size_t)s * KCH;

    const int a_row = lane & 15, a_kh = lane >> 4;
    const int b_row = lane & 7,  b_kh = (lane >> 3) & 1;

    for (int t = 0; t < KCH / KBLK; t++) {
        const int nb = t * KBLK;
        // A: x [128 c x 64 n] f32 -> hi/lo bf16, swizzled
        #pragma unroll
        for (int i = 0; i < 8; i++) {
            int e = tid + i * 256;            // 0..2047 float4s
            int c = e >> 4, q = e & 15;
            float4 v = *(const float4*)(xb + (size_t)c * NPTS + nb + q * 4);
            __nv_bfloat16 h0, l0, h1, l1, h2, l2, h3, l3;
            split2(v.x, h0, l0); split2(v.y, h1, l1);
            split2(v.z, h2, l2); split2(v.w, h3, l3);
            uint32_t off = SWZ128((uint32_t)(c * 128 + q * 8));
            *(uint2*)(smem + AH + off) = make_uint2(pack2(h0, h1), pack2(h2, h3));
            *(uint2*)(smem + AL + off) = make_uint2(pack2(l0, l1), pack2(l2, l3));
        }
        // B: wbT [128 modes x 64 n] bf16, swizzled
        #pragma unroll
        for (int i = 0; i < 4; i++) {
            int e = tid + i * 256;            // 0..1023 16B granules
            int r = e >> 3, g = e & 7;
            uint32_t off = SWZ128((uint32_t)(r * 128 + g * 16));
            *(float4*)(smem + BH + off) = *(const float4*)(wh + (size_t)r * NPTS + nb + g * 8);
            *(float4*)(smem + BL + off) = *(const float4*)(wl + (size_t)r * NPTS + nb + g * 8);
        }
        __syncthreads();

        #pragma unroll
        for (int ks = 0; ks < 4; ks++) {
            uint32_t bh[4][2], bl[4][2];
            #pragma unroll
            for (int ni = 0; ni < 4; ni++) {
                uint32_t off = SWZ128((uint32_t)((n0 + ni * 8 + b_row) * 128 + ks * 32 + b_kh * 16));
                LDSM_X2(bh[ni][0], bh[ni][1], sb + BH + off);
                LDSM_X2(bl[ni][0], bl[ni][1], sb + BL + off);
            }
            #pragma unroll
            for (int mi = 0; mi < 4; mi++) {
                uint32_t off = SWZ128((uint32_t)((m0 + mi * 16 + a_row) * 128 + ks * 32 + a_kh * 16));
                uint32_t ah[4], al[4];
                LDSM_X4(ah[0], ah[1], ah[2], ah[3], sb + AH + off);
                LDSM_X4(al[0], al[1], al[2], al[3], sb + AL + off);
                #pragma unroll
                for (int ni = 0; ni < 4; ni++) {
                    mma16816(acc[mi][ni], ah, bh[ni]);
                    mma16816(acc[mi][ni], ah, bl[ni]);
                    mma16816(acc[mi][ni], al, bh[ni]);
                }
            }
        }
        __syncthreads();
    }

    // epilogue -> g_part
    const int gid = lane >> 2, tg = lane & 3;
    float* dst = g_part + (size_t)(s * BB + b) * CI * KM;
    #pragma unroll
    for (int mi = 0; mi < 4; mi++)
        #pragma unroll
        for (int ni = 0; ni < 4; ni++) {
            int row = m0 + mi * 16 + gid;
            int col = n0 + ni * 8 + tg * 2;
            *(float2*)(dst + (size_t)row * KM + col) =
                make_float2(acc[mi][ni][0], acc[mi][ni][1]);
            *(float2*)(dst + (size_t)(row + 8) * KM + col) =
                make_float2(acc[mi][ni][2], acc[mi][ni][3]);
        }
}

// ---------------------------------------------------------------------------
// Deterministic split-K reduction
// ---------------------------------------------------------------------------
__global__ __launch_bounds__(256) void reduce_kernel() {
    int idx = blockIdx.x * 256 + threadIdx.x;
    float sum = 0.0f;
    #pragma unroll
    for (int p = 0; p < NSPLIT; p++)
        sum += g_part[(size_t)p * (BB * CI * KM) + idx];
    g_xco[idx] = sum;
}

// ---------------------------------------------------------------------------
// mix: x_hat[b,o,k] = sum_i x_co[b,i,k] * W[i,o,k]; emit bf16 hi/lo
// ---------------------------------------------------------------------------
__global__ __launch_bounds__(128) void mix_kernel(const float* __restrict__ W) {
    const int o = blockIdx.x, b = blockIdx.y, k = threadIdx.x;
    const float* xc = g_xco + (size_t)b * CI * KM;
    const float* w  = W + (size_t)o * KM;
    float sv = 0.0f;
    #pragma unroll 8
    for (int i = 0; i < CI; i++)
        sv = fmaf(xc[(size_t)i * KM + k], w[(size_t)i * CO * KM + k], sv);
    __nv_bfloat16 h, l; split2(sv, h, l);
    size_t idx = ((size_t)b * CO + o) * KM + k;
    g_xhat_hi[idx] = h;
    g_xhat_lo[idx] = l;
}

// ---------------------------------------------------------------------------
// GEMM3: out[b, o, x0:x0+256] = x_hat[b] @ bases[x0:x0+256, :]^T
//   M=128 (o), N=256 (n), K=128. 8 warps as 2(M)x4(N): warp tile 64x64.
// ---------------------------------------------------------------------------
#define G3_AH 0
#define G3_AL 32768
#define G3_BH 65536
#define G3_BL (65536 + 65536)
#define G3_SMEM (G3_BL + 65536)
__global__ __launch_bounds__(256) void gemm3_kernel(float* __restrict__ out) {
    extern __shared__ __align__(128) char smem[];
    const uint32_t sb = smem_u32(smem);
    const int x0 = blockIdx.x * 256, b = blockIdx.y;
    const int tid = threadIdx.x, wid = tid >> 5, lane = tid & 31;
    const int m0 = (wid >> 2) * 64, n0 = (wid & 3) * 64;

    // A: x_hat hi/lo [128 o x 128 k] bf16, 256B rows, swizzled
    const __nv_bfloat16* xh = g_xhat_hi + (size_t)b * CO * KM;
    const __nv_bfloat16* xl = g_xhat_lo + (size_t)b * CO * KM;
    #pragma unroll
    for (int i = 0; i < 8; i++) {
        int e = tid + i * 256;               // 0..2047 granules
        int r = e >> 4, g = e & 15;
        uint32_t off = SWZ256((uint32_t)(r * 256 + g * 16));
        *(float4*)(smem + G3_AH + off) = *(const float4*)(xh + (size_t)r * KM + g * 8);
        *(float4*)(smem + G3_AL + off) = *(const float4*)(xl + (size_t)r * KM + g * 8);
    }
    // B: bases hi/lo [256 n x 128 k] bf16, 256B rows, swizzled
    #pragma unroll
    for (int i = 0; i < 16; i++) {
        int e = tid + i * 256;               // 0..4095 granules
        int r = e >> 4, g = e & 15;
        uint32_t off = SWZ256((uint32_t)(r * 256 + g * 16));
        *(float4*)(smem + G3_BH + off) = *(const float4*)(g_ba_hi + (size_t)(x0 + r) * KM + g * 8);
        *(float4*)(smem + G3_BL + off) = *(const float4*)(g_ba_lo + (size_t)(x0 + r) * KM + g * 8);
    }
    __syncthreads();

    float acc[4][8][4];
    #pragma unroll
    for (int mi = 0; mi < 4; mi++)
        #pragma unroll
        for (int ni = 0; ni < 8; ni++)
            #pragma unroll
            for (int j = 0; j < 4; j++) acc[mi][ni][j] = 0.0f;

    const int a_row = lane & 15, a_kh = lane >> 4;
    const int b_row = lane & 7,  b_kh = (lane >> 3) & 1;

    #pragma unroll
    for (int ks = 0; ks < 8; ks++) {
        uint32_t ah[4][4], al[4][4];
        #pragma unroll
        for (int mi = 0; mi < 4; mi++) {
            uint32_t off = SWZ256((uint32_t)((m0 + mi * 16 + a_row) * 256 + ks * 32 + a_kh * 16));
            LDSM_X4(ah[mi][0], ah[mi][1], ah[mi][2], ah[mi][3], sb + G3_AH + off);
            LDSM_X4(al[mi][0], al[mi][1], al[mi][2], al[mi][3], sb + G3_AL + off);
        }
        #pragma unroll
        for (int ni = 0; ni < 8; ni++) {
            uint32_t off = SWZ256((uint32_t)((n0 + ni * 8 + b_row) * 256 + ks * 32 + b_kh * 16));
            uint32_t bh[2], bl[2];
            LDSM_X2(bh[0], bh[1], sb + G3_BH + off);
            LDSM_X2(bl[0], bl[1], sb + G3_BL + off);
            #pragma unroll
            for (int mi = 0; mi < 4; mi++) {
                mma16816(acc[mi][ni], ah[mi], bh);
                mma16816(acc[mi][ni], ah[mi], bl);
                mma16816(acc[mi][ni], al[mi], bh);
            }
        }
    }

    // epilogue -> out (f32)
    const int gid = lane >> 2, tg = lane & 3;
    float* ob = out + (size_t)b * CO * NPTS + x0;
    #pragma unroll
    for (int mi = 0; mi < 4; mi++)
        #pragma unroll
        for (int ni = 0; ni < 8; ni++) {
            int row = m0 + mi * 16 + gid;
            int col = n0 + ni * 8 + tg * 2;
            *(float2*)(ob + (size_t)row * NPTS + col) =
                make_float2(acc[mi][ni][0], acc[mi][ni][1]);
            *(float2*)(ob + (size_t)(row + 8) * NPTS + col) =
                make_float2(acc[mi][ni][2], acc[mi][ni][3]);
        }
}

// ---------------------------------------------------------------------------
extern "C" void kernel_launch(void* const* d_in, const int* in_sizes, int n_in,
                              void* d_out, int out_size) {
    const float* x  = (const float*)d_in[0];   // [16,128,16384]
    const float* wb = (const float*)d_in[1];   // wbases [16384,128]
    const float* ba = (const float*)d_in[2];   // bases  [16384,128]
    const float* W  = (const float*)d_in[3];   // [128,128,128]
    float* out = (float*)d_out;                // [16,128,16384]

    cudaFuncSetAttribute(gemm1_kernel, cudaFuncAttributeMaxDynamicSharedMemorySize, G1_SMEM);
    cudaFuncSetAttribute(gemm3_kernel, cudaFuncAttributeMaxDynamicSharedMemorySize, G3_SMEM);

    prep_wb<<<dim3(NPTS / 32, KM / 32), dim3(32, 8)>>>(wb);
    prep_ba<<<(NPTS * KM) / 256, 256>>>(ba);
    gemm1_kernel<<<dim3(NSPLIT, BB), 256, G1_SMEM>>>(x);
    reduce_kernel<<<(BB * CI * KM) / 256, 256>>>();
    mix_kernel<<<dim3(CO, BB), 128>>>(W);
    gemm3_kernel<<<dim3(NPTS / 256, BB), 256, G3_SMEM>>>(out);
}

// round 8
// speedup vs baseline: 1.2911x; 1.0036x over previous
#include <cuda_runtime.h>
#include <cuda_bf16.h>
#include <cstdint>

// GalerkinConv via mma.sync bf16 3-term split GEMMs, cp.async double-buffered
// B=16, C_IN=128, C_OUT=128, N=16384, MODES=128
#define BB 16
#define CI 128
#define CO 128
#define NPTS 16384
#define KM 128
#define NSPLIT 16
#define KCH (NPTS / NSPLIT)   // 1024 n per GEMM1 CTA
#define KBLK 64
#define NITER (KCH / KBLK)    // 16

// ---------------- scratch (static device globals; no allocation) ----------
__device__ float         g_part[NSPLIT * BB * CI * KM];   // 16.8 MB
__device__ float         g_xco [BB * CI * KM];
__device__ __nv_bfloat16 g_xhat_hi[BB * CO * KM];
__device__ __nv_bfloat16 g_xhat_lo[BB * CO * KM];
__device__ __nv_bfloat16 g_wbT_hi[KM * NPTS];             // wbases^T, [mode][n]
__device__ __nv_bfloat16 g_wbT_lo[KM * NPTS];
__device__ __nv_bfloat16 g_ba_hi[NPTS * KM];              // bases, [n][k]
__device__ __nv_bfloat16 g_ba_lo[NPTS * KM];

// ---------------- helpers --------------------------------------------------
__device__ __forceinline__ uint32_t smem_u32(const void* p) {
    uint32_t a;
    asm("{ .reg .u64 t; cvta.to.shared.u64 t, %1; cvt.u32.u64 %0, t; }"
        : "=r"(a) : "l"(p));
    return a;
}

#define SWZ128(o) ((o) ^ (((o) >> 3) & 0x70))   // 128B rows
#define SWZ256(o) ((o) ^ (((o) >> 4) & 0x70))   // 256B rows

#define LDSM_X4(r0, r1, r2, r3, a) \
    asm volatile("ldmatrix.sync.aligned.m8n8.x4.shared.b16 {%0,%1,%2,%3}, [%4];" \
                 : "=r"(r0), "=r"(r1), "=r"(r2), "=r"(r3) : "r"(a))
#define LDSM_X2(r0, r1, a) \
    asm volatile("ldmatrix.sync.aligned.m8n8.x2.shared.b16 {%0,%1}, [%2];" \
                 : "=r"(r0), "=r"(r1) : "r"(a))

#define CP16(dst_u32, src_ptr) \
    asm volatile("cp.async.cg.shared.global [%0], [%1], 16;" \
                 :: "r"(dst_u32), "l"(src_ptr))
#define CP_COMMIT asm volatile("cp.async.commit_group;" ::: "memory")
#define CP_WAIT(n) asm volatile("cp.async.wait_group %0;" :: "n"(n) : "memory")

__device__ __forceinline__ void mma16816(float* d, const uint32_t* a, const uint32_t* b) {
    asm volatile(
        "mma.sync.aligned.m16n8k16.row.col.f32.bf16.bf16.f32 "
        "{%0,%1,%2,%3}, {%4,%5,%6,%7}, {%8,%9}, {%0,%1,%2,%3};"
        : "+f"(d[0]), "+f"(d[1]), "+f"(d[2]), "+f"(d[3])
        : "r"(a[0]), "r"(a[1]), "r"(a[2]), "r"(a[3]), "r"(b[0]), "r"(b[1]));
}

__device__ __forceinline__ void split2(float v, __nv_bfloat16& h, __nv_bfloat16& l) {
    h = __float2bfloat16(v);
    l = __float2bfloat16(v - __bfloat162float(h));
}
__device__ __forceinline__ uint32_t pack2(__nv_bfloat16 a, __nv_bfloat16 b) {
    return (uint32_t)__bfloat16_as_ushort(a) | ((uint32_t)__bfloat16_as_ushort(b) << 16);
}

// ---------------------------------------------------------------------------
// preps
// ---------------------------------------------------------------------------
__global__ void prep_wb(const float* __restrict__ wb) {
    __shared__ float t[32][33];
    const int n0 = blockIdx.x * 32, k0 = blockIdx.y * 32;
    const int tx = threadIdx.x, ty = threadIdx.y;   // (32, 8)
    #pragma unroll
    for (int i = 0; i < 4; i++)
        t[ty + i * 8][tx] = wb[(size_t)(n0 + ty + i * 8) * KM + k0 + tx];
    __syncthreads();
    #pragma unroll
    for (int i = 0; i < 4; i++) {
        float v = t[tx][ty + i * 8];
        __nv_bfloat16 h, l; split2(v, h, l);
        size_t idx = (size_t)(k0 + ty + i * 8) * NPTS + n0 + tx;
        g_wbT_hi[idx] = h;
        g_wbT_lo[idx] = l;
    }
}

__global__ void prep_ba(const float* __restrict__ ba) {
    int i = (blockIdx.x * 256 + threadIdx.x) * 4;
    float4 v = *(const float4*)(ba + i);
    __nv_bfloat16 h0, l0, h1, l1, h2, l2, h3, l3;
    split2(v.x, h0, l0); split2(v.y, h1, l1);
    split2(v.z, h2, l2); split2(v.w, h3, l3);
    *(uint2*)(g_ba_hi + i) = make_uint2(pack2(h0, h1), pack2(h2, h3));
    *(uint2*)(g_ba_lo + i) = make_uint2(pack2(l0, l1), pack2(l2, l3));
}

// ---------------------------------------------------------------------------
// GEMM1: partial[s][b] = x[b,:,s*1024:(s+1)*1024] @ wbases-chunk
//   M=128(c) x N=128(modes) x K=1024 in 16 blocks of 64, double-buffered.
//   Stage layout (64KB): Ah@0 Al@16K Bh@32K Bl@48K.
// ---------------------------------------------------------------------------
#define G1_STAGE 65536
#define G1_SMEM (2 * G1_STAGE)

__device__ __forceinline__ void g1_loadx(float4* pre, const float* xb, int t, int tid) {
    #pragma unroll
    for (int i = 0; i < 8; i++) {
        int e = tid + i * 256;
        int c = e >> 4, q = e & 15;
        pre[i] = *(const float4*)(xb + (size_t)c * NPTS + t * KBLK + q * 4);
    }
}
__device__ __forceinline__ void g1_conva(char* smem, int st, const float4* pre, int tid) {
    char* base = smem + st * G1_STAGE;
    #pragma unroll
    for (int i = 0; i < 8; i++) {
        int e = tid + i * 256;
        int c = e >> 4, q = e & 15;
        __nv_bfloat16 h0, l0, h1, l1, h2, l2, h3, l3;
        split2(pre[i].x, h0, l0); split2(pre[i].y, h1, l1);
        split2(pre[i].z, h2, l2); split2(pre[i].w, h3, l3);
        uint32_t off = SWZ128((uint32_t)(c * 128 + q * 8));
        *(uint2*)(base + off)         = make_uint2(pack2(h0, h1), pack2(h2, h3));
        *(uint2*)(base + 16384 + off) = make_uint2(pack2(l0, l1), pack2(l2, l3));
    }
}
__device__ __forceinline__ void g1_loadb(uint32_t sb, int st,
                                         const __nv_bfloat16* wh,
                                         const __nv_bfloat16* wl, int t, int tid) {
    uint32_t base = sb + st * G1_STAGE;
    #pragma unroll
    for (int i = 0; i < 4; i++) {
        int e = tid + i * 256;
        int r = e >> 3, g = e & 7;
        uint32_t off = SWZ128((uint32_t)(r * 128 + g * 16));
        CP16(base + 32768 + off, wh + (size_t)r * NPTS + t * KBLK + g * 8);
        CP16(base + 49152 + off, wl + (size_t)r * NPTS + t * KBLK + g * 8);
    }
}
__device__ __forceinline__ void g1_compute(uint32_t sb, int st, float acc[4][4][4],
                                           int m0, int n0, int lane) {
    const uint32_t base = sb + st * G1_STAGE;
    const int a_row = lane & 15, a_kh = lane >> 4;
    const int b_row = lane & 7,  b_kh = (lane >> 3) & 1;
    #pragma unroll
    for (int ks = 0; ks < 4; ks++) {
        uint32_t bh[4][2], bl[4][2], ah[4][4], al[4][4];
        #pragma unroll
        for (int ni = 0; ni < 4; ni++) {
            uint32_t off = SWZ128((uint32_t)((n0 + ni * 8 + b_row) * 128 + ks * 32 + b_kh * 16));
            LDSM_X2(bh[ni][0], bh[ni][1], base + 32768 + off);
            LDSM_X2(bl[ni][0], bl[ni][1], base + 49152 + off);
        }
        #pragma unroll
        for (int mi = 0; mi < 4; mi++) {
            uint32_t off = SWZ128((uint32_t)((m0 + mi * 16 + a_row) * 128 + ks * 32 + a_kh * 16));
            LDSM_X4(ah[mi][0], ah[mi][1], ah[mi][2], ah[mi][3], base + off);
            LDSM_X4(al[mi][0], al[mi][1], al[mi][2], al[mi][3], base + 16384 + off);
        }
        // term-major: no accumulator RAW chains
        #pragma unroll
        for (int mi = 0; mi < 4; mi++)
            #pragma unroll
            for (int ni = 0; ni < 4; ni++) mma16816(acc[mi][ni], ah[mi], bh[ni]);
        #pragma unroll
        for (int mi = 0; mi < 4; mi++)
            #pragma unroll
            for (int ni = 0; ni < 4; ni++) mma16816(acc[mi][ni], ah[mi], bl[ni]);
        #pragma unroll
        for (int mi = 0; mi < 4; mi++)
            #pragma unroll
            for (int ni = 0; ni < 4; ni++) mma16816(acc[mi][ni], al[mi], bh[ni]);
    }
}

__global__ __launch_bounds__(256, 1) void gemm1_kernel(const float* __restrict__ x) {
    extern __shared__ __align__(128) char smem[];
    const uint32_t sb = smem_u32(smem);
    const int s = blockIdx.x, b = blockIdx.y;
    const int tid = threadIdx.x, wid = tid >> 5, lane = tid & 31;
    const int m0 = (wid >> 2) * 64, n0 = (wid & 3) * 32;

    float acc[4][4][4];
    #pragma unroll
    for (int mi = 0; mi < 4; mi++)
        #pragma unroll
        for (int ni = 0; ni < 4; ni++)
            #pragma unroll
            for (int j = 0; j < 4; j++) acc[mi][ni][j] = 0.0f;

    const float* xb = x + (size_t)b * CI * NPTS + (size_t)s * KCH;
    const __nv_bfloat16* wh = g_wbT_hi + (size_t)s * KCH;
    const __nv_bfloat16* wl = g_wbT_lo + (size_t)s * KCH;

    float4 pre[8];
    // prologue
    g1_loadx(pre, xb, 0, tid);
    g1_loadb(sb, 0, wh, wl, 0, tid); CP_COMMIT;
    g1_conva(smem, 0, pre, tid);
    g1_loadx(pre, xb, 1, tid);
    CP_WAIT(0);
    __syncthreads();

    for (int t = 0; t < NITER; t++) {
        const int cur = t & 1, nxt = cur ^ 1;
        if (t + 1 < NITER) { g1_loadb(sb, nxt, wh, wl, t + 1, tid); CP_COMMIT; }
        g1_compute(sb, cur, acc, m0, n0, lane);
        if (t + 1 < NITER) {
            g1_conva(smem, nxt, pre, tid);
            if (t + 2 < NITER) g1_loadx(pre, xb, t + 2, tid);
            CP_WAIT(0);
        }
        __syncthreads();
    }

    // epilogue -> g_part
    const int gid = lane >> 2, tg = lane & 3;
    float* dst = g_part + (size_t)(s * BB + b) * CI * KM;
    #pragma unroll
    for (int mi = 0; mi < 4; mi++)
        #pragma unroll
        for (int ni = 0; ni < 4; ni++) {
            int row = m0 + mi * 16 + gid;
            int col = n0 + ni * 8 + tg * 2;
            *(float2*)(dst + (size_t)row * KM + col) =
                make_float2(acc[mi][ni][0], acc[mi][ni][1]);
            *(float2*)(dst + (size_t)(row + 8) * KM + col) =
                make_float2(acc[mi][ni][2], acc[mi][ni][3]);
        }
}

// ---------------------------------------------------------------------------
// Deterministic split-K reduction (float4)
// ---------------------------------------------------------------------------
__global__ __launch_bounds__(256) void reduce_kernel() {
    int idx = (blockIdx.x * 256 + threadIdx.x) * 4;
    float4 s = make_float4(0.f, 0.f, 0.f, 0.f);
    #pragma unroll
    for (int p = 0; p < NSPLIT; p++) {
        float4 v = *(const float4*)(g_part + (size_t)p * (BB * CI * KM) + idx);
        s.x += v.x; s.y += v.y; s.z += v.z; s.w += v.w;
    }
    *(float4*)(g_xco + idx) = s;
}

// ---------------------------------------------------------------------------
// mix: x_hat[b,o,k] = sum_i x_co[b,i,k] * W[i,o,k]; 4o x 4b tiles
// ---------------------------------------------------------------------------
__global__ __launch_bounds__(128) void mix_kernel(const float* __restrict__ W) {
    const int o0 = blockIdx.x * 4, b0 = blockIdx.y * 4;   // grid (32, 4)
    const int k = threadIdx.x;
    float acc[4][4];
    #pragma unroll
    for (int oo = 0; oo < 4; oo++)
        #pragma unroll
        for (int bb = 0; bb < 4; bb++) acc[oo][bb] = 0.0f;

    for (int i = 0; i < CI; i++) {
        float wv[4], xv[4];
        #pragma unroll
        for (int oo = 0; oo < 4; oo++)
            wv[oo] = W[((size_t)i * CO + o0 + oo) * KM + k];
        #pragma unroll
        for (int bb = 0; bb < 4; bb++)
            xv[bb] = g_xco[((size_t)(b0 + bb) * CI + i) * KM + k];
        #pragma unroll
        for (int oo = 0; oo < 4; oo++)
            #pragma unroll
            for (int bb = 0; bb < 4; bb++)
                acc[oo][bb] = fmaf(xv[bb], wv[oo], acc[oo][bb]);
    }
    #pragma unroll
    for (int oo = 0; oo < 4; oo++)
        #pragma unroll
        for (int bb = 0; bb < 4; bb++) {
            __nv_bfloat16 h, l; split2(acc[oo][bb], h, l);
            size_t idx = ((size_t)(b0 + bb) * CO + o0 + oo) * KM + k;
            g_xhat_hi[idx] = h;
            g_xhat_lo[idx] = l;
        }
}

// ---------------------------------------------------------------------------
// GEMM3: out[b, o, :] = x_hat[b] @ bases^T.  Grid (32, 16): each CTA loads
//   A (x_hat, 64KB) once and streams 4 jobs of N=128 with double-buffered B.
//   smem: Ah@0 Al@32K, stage s: Bh@64K+s*64K Bl@+32K.  Total 192KB.
// ---------------------------------------------------------------------------
#define G3_B0 65536
#define G3_BSTAGE 65536
#define G3_SMEM (G3_B0 + 2 * G3_BSTAGE)

__device__ __forceinline__ void g3_loadb(uint32_t sb, int st, int x0, int tid) {
    uint32_t base = sb + G3_B0 + st * G3_BSTAGE;
    #pragma unroll
    for (int i = 0; i < 8; i++) {
        int e = tid + i * 256;
        int r = e >> 4, g = e & 15;
        uint32_t off = SWZ256((uint32_t)(r * 256 + g * 16));
        CP16(base + off,         g_ba_hi + (size_t)(x0 + r) * KM + g * 8);
        CP16(base + 32768 + off, g_ba_lo + (size_t)(x0 + r) * KM + g * 8);
    }
}

__global__ __launch_bounds__(256, 1) void gemm3_kernel(float* __restrict__ out) {
    extern __shared__ __align__(128) char smem[];
    const uint32_t sb = smem_u32(smem);
    const int bx = blockIdx.x, b = blockIdx.y;
    const int tid = threadIdx.x, wid = tid >> 5, lane = tid & 31;
    const int m0 = (wid >> 2) * 64, n0 = (wid & 3) * 32;

    // A load (once): x_hat hi/lo [128 o x 128 k]
    const __nv_bfloat16* xh = g_xhat_hi + (size_t)b * CO * KM;
    const __nv_bfloat16* xl = g_xhat_lo + (size_t)b * CO * KM;
    #pragma unroll
    for (int i = 0; i < 8; i++) {
        int e = tid + i * 256;
        int r = e >> 4, g = e & 15;
        uint32_t off = SWZ256((uint32_t)(r * 256 + g * 16));
        CP16(sb + off,         xh + (size_t)r * KM + g * 8);
        CP16(sb + 32768 + off, xl + (size_t)r * KM + g * 8);
    }
    g3_loadb(sb, 0, (bx * 4 + 0) * 128, tid);
    CP_COMMIT;
    g3_loadb(sb, 1, (bx * 4 + 1) * 128, tid);
    CP_COMMIT;
    CP_WAIT(1);      // A + B0 done
    __syncthreads();

    const int a_row = lane & 15, a_kh = lane >> 4;
    const int b_row = lane & 7,  b_kh = (lane >> 3) & 1;
    const int gid = lane >> 2, tg = lane & 3;

    for (int j = 0; j < 4; j++) {
        const int st = j & 1;
        const uint32_t bbase = sb + G3_B0 + st * G3_BSTAGE;

        float acc[4][4][4];
        #pragma unroll
        for (int mi = 0; mi < 4; mi++)
            #pragma unroll
            for (int ni = 0; ni < 4; ni++)
                #pragma unroll
                for (int q = 0; q < 4; q++) acc[mi][ni][q] = 0.0f;

        #pragma unroll
        for (int ks = 0; ks < 8; ks++) {
            uint32_t ah[4][4], al[4][4], bh[4][2], bl[4][2];
            #pragma unroll
            for (int mi = 0; mi < 4; mi++) {
                uint32_t off = SWZ256((uint32_t)((m0 + mi * 16 + a_row) * 256 + ks * 32 + a_kh * 16));
                LDSM_X4(ah[mi][0], ah[mi][1], ah[mi][2], ah[mi][3], sb + off);
                LDSM_X4(al[mi][0], al[mi][1], al[mi][2], al[mi][3], sb + 32768 + off);
            }
            #pragma unroll
            for (int ni = 0; ni < 4; ni++) {
                uint32_t off = SWZ256((uint32_t)((n0 + ni * 8 + b_row) * 256 + ks * 32 + b_kh * 16));
                LDSM_X2(bh[ni][0], bh[ni][1], bbase + off);
                LDSM_X2(bl[ni][0], bl[ni][1], bbase + 32768 + off);
            }
            #pragma unroll
            for (int mi = 0; mi < 4; mi++)
                #pragma unroll
                for (int ni = 0; ni < 4; ni++) mma16816(acc[mi][ni], ah[mi], bh[ni]);
            #pragma unroll
            for (int mi = 0; mi < 4; mi++)
                #pragma unroll
                for (int ni = 0; ni < 4; ni++) mma16816(acc[mi][ni], ah[mi], bl[ni]);
            #pragma unroll
            for (int mi = 0; mi < 4; mi++)
                #pragma unroll
                for (int ni = 0; ni < 4; ni++) mma16816(acc[mi][ni], al[mi], bh[ni]);
        }
        __syncthreads();                      // all warps done reading stage st
        if (j + 2 < 4) { g3_loadb(sb, st, (bx * 4 + j + 2) * 128, tid); CP_COMMIT; }

        // epilogue for job j (overlaps cp.async)
        const int x0 = (bx * 4 + j) * 128;
        float* ob = out + (size_t)b * CO * NPTS + x0;
        #pragma unroll
        for (int mi = 0; mi < 4; mi++)
            #pragma unroll
            for (int ni = 0; ni < 4; ni++) {
                int row = m0 + mi * 16 + gid;
                int col = n0 + ni * 8 + tg * 2;
                *(float2*)(ob + (size_t)row * NPTS + col) =
                    make_float2(acc[mi][ni][0], acc[mi][ni][1]);
                *(float2*)(ob + (size_t)(row + 8) * NPTS + col) =
                    make_float2(acc[mi][ni][2], acc[mi][ni][3]);
            }

        if (j + 1 < 4) {
            if (j + 2 < 4) { CP_WAIT(1); } else { CP_WAIT(0); }
            __syncthreads();
        }
    }
}

// ---------------------------------------------------------------------------
extern "C" void kernel_launch(void* const* d_in, const int* in_sizes, int n_in,
                              void* d_out, int out_size) {
    const float* x  = (const float*)d_in[0];   // [16,128,16384]
    const float* wb = (const float*)d_in[1];   // wbases [16384,128]
    const float* ba = (const float*)d_in[2];   // bases  [16384,128]
    const float* W  = (const float*)d_in[3];   // [128,128,128]
    float* out = (float*)d_out;                // [16,128,16384]

    cudaFuncSetAttribute(gemm1_kernel, cudaFuncAttributeMaxDynamicSharedMemorySize, G1_SMEM);
    cudaFuncSetAttribute(gemm3_kernel, cudaFuncAttributeMaxDynamicSharedMemorySize, G3_SMEM);

    prep_wb<<<dim3(NPTS / 32, KM / 32), dim3(32, 8)>>>(wb);
    prep_ba<<<(NPTS * KM) / 1024, 256>>>(ba);
    gemm1_kernel<<<dim3(NSPLIT, BB), 256, G1_SMEM>>>(x);
    reduce_kernel<<<(BB * CI * KM) / 1024, 256>>>();
    mix_kernel<<<dim3(CO / 4, BB / 4), 128>>>(W);
    gemm3_kernel<<<dim3(NPTS / 512, BB), 256, G3_SMEM>>>(out);
}

// round 11
// speedup vs baseline: 1.6586x; 1.2847x over previous
#include <cuda_runtime.h>
#include <cuda_fp16.h>
#include <cstdint>

// GalerkinConv via mma.sync fp16 2-term split GEMMs (sm_103 baseline ISA)
// B=16, C_IN=128, C_OUT=128, N=16384, MODES=128
#define BB 16
#define CI 128
#define CO 128
#define NPTS 16384
#define KM 128
#define NSPLIT 16
#define KCH (NPTS / NSPLIT)   // 1024 n per GEMM1 CTA
#define KBLK 64
#define NITER (KCH / KBLK)    // 16

// ---------------- scratch (static device globals; no allocation) ----------
__device__ float  g_part[NSPLIT * BB * CI * KM];   // 16.8 MB
__device__ float  g_xco [BB * CI * KM];
__device__ __half g_xhat_hi[BB * CO * KM];
__device__ __half g_xhat_lo[BB * CO * KM];
__device__ __half g_wbT_hi[KM * NPTS];             // wbases^T hi limb, [mode][n]
__device__ __half g_wbT_lo[KM * NPTS];             // wbases^T lo limb
__device__ __half g_ba[NPTS * KM];                 // bases single fp16, [n][k]

// ---------------- helpers --------------------------------------------------
__device__ __forceinline__ uint32_t smem_u32(const void* p) {
    uint32_t a;
    asm("{ .reg .u64 t; cvta.to.shared.u64 t, %1; cvt.u32.u64 %0, t; }"
        : "=r"(a) : "l"(p));
    return a;
}

#define SWZ128(o) ((o) ^ (((o) >> 3) & 0x70))   // 128B rows
#define SWZ256(o) ((o) ^ (((o) >> 4) & 0x70))   // 256B rows

#define LDSM_X4(r0, r1, r2, r3, a) \
    asm volatile("ldmatrix.sync.aligned.m8n8.x4.shared.b16 {%0,%1,%2,%3}, [%4];" \
                 : "=r"(r0), "=r"(r1), "=r"(r2), "=r"(r3) : "r"(a))
#define LDSM_X2(r0, r1, a) \
    asm volatile("ldmatrix.sync.aligned.m8n8.x2.shared.b16 {%0,%1}, [%2];" \
                 : "=r"(r0), "=r"(r1) : "r"(a))

#define CP16(dst_u32, src_ptr) \
    asm volatile("cp.async.cg.shared.global [%0], [%1], 16;" \
                 :: "r"(dst_u32), "l"(src_ptr))
#define CP_COMMIT asm volatile("cp.async.commit_group;" ::: "memory")
#define CP_WAIT(n) asm volatile("cp.async.wait_group %0;" :: "n"(n) : "memory")

__device__ __forceinline__ void mma16816h(float* d, const uint32_t* a, const uint32_t* b) {
    asm volatile(
        "mma.sync.aligned.m16n8k16.row.col.f32.f16.f16.f32 "
        "{%0,%1,%2,%3}, {%4,%5,%6,%7}, {%8,%9}, {%0,%1,%2,%3};"
        : "+f"(d[0]), "+f"(d[1]), "+f"(d[2]), "+f"(d[3])
        : "r"(a[0]), "r"(a[1]), "r"(a[2]), "r"(a[3]), "r"(b[0]), "r"(b[1]));
}

__device__ __forceinline__ void split2h(float v, __half& h, __half& l) {
    h = __float2half(v);
    l = __float2half(v - __half2float(h));
}
__device__ __forceinline__ uint32_t pack2h(__half a, __half b) {
    return (uint32_t)__half_as_ushort(a) | ((uint32_t)__half_as_ushort(b) << 16);
}

// ---------------------------------------------------------------------------
// preps
// ---------------------------------------------------------------------------
__global__ void prep_wb(const float* __restrict__ wb) {
    __shared__ float t[32][33];
    const int n0 = blockIdx.x * 32, k0 = blockIdx.y * 32;
    const int tx = threadIdx.x, ty = threadIdx.y;   // (32, 8)
    #pragma unroll
    for (int i = 0; i < 4; i++)
        t[ty + i * 8][tx] = wb[(size_t)(n0 + ty + i * 8) * KM + k0 + tx];
    __syncthreads();
    #pragma unroll
    for (int i = 0; i < 4; i++) {
        float v = t[tx][ty + i * 8];
        __half h, l; split2h(v, h, l);
        size_t idx = (size_t)(k0 + ty + i * 8) * NPTS + n0 + tx;
        g_wbT_hi[idx] = h;
        g_wbT_lo[idx] = l;
    }
}

__global__ void prep_ba(const float* __restrict__ ba) {
    int i = (blockIdx.x * 256 + threadIdx.x) * 4;
    float4 v = *(const float4*)(ba + i);
    *(uint2*)(g_ba + i) = make_uint2(
        pack2h(__float2half(v.x), __float2half(v.y)),
        pack2h(__float2half(v.z), __float2half(v.w)));
}

// ---------------------------------------------------------------------------
// GEMM1: partial[s][b] = x[b,:,chunk] @ wbases-chunk
//   M=128(c) x N=128(modes) x K=1024 in 16 blocks of 64, double-buffered.
//   A = fp16(x) single limb; B = wbT hi+lo.  Stage 48KB: A@0 Bh@16K Bl@32K.
// ---------------------------------------------------------------------------
#define G1_STAGE 49152
#define G1_SMEM (2 * G1_STAGE)

__device__ __forceinline__ void g1_loadx(float4* pre, const float* xb, int t, int tid) {
    #pragma unroll
    for (int i = 0; i < 8; i++) {
        int e = tid + i * 256;
        int c = e >> 4, q = e & 15;
        pre[i] = *(const float4*)(xb + (size_t)c * NPTS + t * KBLK + q * 4);
    }
}
__device__ __forceinline__ void g1_conva(char* smem, int st, const float4* pre, int tid) {
    char* base = smem + st * G1_STAGE;
    #pragma unroll
    for (int i = 0; i < 8; i++) {
        int e = tid + i * 256;
        int c = e >> 4, q = e & 15;
        uint32_t off = SWZ128((uint32_t)(c * 128 + q * 8));
        *(uint2*)(base + off) = make_uint2(
            pack2h(__float2half(pre[i].x), __float2half(pre[i].y)),
            pack2h(__float2half(pre[i].z), __float2half(pre[i].w)));
    }
}
__device__ __forceinline__ void g1_loadb(uint32_t sb, int st,
                                         const __half* wh, const __half* wl,
                                         int t, int tid) {
    uint32_t base = sb + st * G1_STAGE;
    #pragma unroll
    for (int i = 0; i < 4; i++) {
        int e = tid + i * 256;
        int r = e >> 3, g = e & 7;
        uint32_t off = SWZ128((uint32_t)(r * 128 + g * 16));
        CP16(base + 16384 + off, wh + (size_t)r * NPTS + t * KBLK + g * 8);
        CP16(base + 32768 + off, wl + (size_t)r * NPTS + t * KBLK + g * 8);
    }
}
__device__ __forceinline__ void g1_compute(uint32_t sb, int st, float acc[4][4][4],
                                           int m0, int n0, int lane) {
    const uint32_t base = sb + st * G1_STAGE;
    const int a_row = lane & 15, a_kh = lane >> 4;
    const int b_row = lane & 7,  b_kh = (lane >> 3) & 1;
    #pragma unroll
    for (int ks = 0; ks < 4; ks++) {
        uint32_t bh[4][2], bl[4][2], a[4][4];
        #pragma unroll
        for (int ni = 0; ni < 4; ni++) {
            uint32_t off = SWZ128((uint32_t)((n0 + ni * 8 + b_row) * 128 + ks * 32 + b_kh * 16));
            LDSM_X2(bh[ni][0], bh[ni][1], base + 16384 + off);
            LDSM_X2(bl[ni][0], bl[ni][1], base + 32768 + off);
        }
        #pragma unroll
        for (int mi = 0; mi < 4; mi++) {
            uint32_t off = SWZ128((uint32_t)((m0 + mi * 16 + a_row) * 128 + ks * 32 + a_kh * 16));
            LDSM_X4(a[mi][0], a[mi][1], a[mi][2], a[mi][3], base + off);
        }
        #pragma unroll
        for (int mi = 0; mi < 4; mi++)
            #pragma unroll
            for (int ni = 0; ni < 4; ni++) mma16816h(acc[mi][ni], a[mi], bh[ni]);
        #pragma unroll
        for (int mi = 0; mi < 4; mi++)
            #pragma unroll
            for (int ni = 0; ni < 4; ni++) mma16816h(acc[mi][ni], a[mi], bl[ni]);
    }
}

__global__ __launch_bounds__(256, 1) void gemm1_kernel(const float* __restrict__ x) {
    extern __shared__ __align__(128) char smem[];
    const uint32_t sb = smem_u32(smem);
    const int s = blockIdx.x, b = blockIdx.y;
    const int tid = threadIdx.x, wid = tid >> 5, lane = tid & 31;
    const int m0 = (wid >> 2) * 64, n0 = (wid & 3) * 32;

    float acc[4][4][4];
    #pragma unroll
    for (int mi = 0; mi < 4; mi++)
        #pragma unroll
        for (int ni = 0; ni < 4; ni++)
            #pragma unroll
            for (int j = 0; j < 4; j++) acc[mi][ni][j] = 0.0f;

    const float* xb = x + (size_t)b * CI * NPTS + (size_t)s * KCH;
    const __half* wh = g_wbT_hi + (size_t)s * KCH;
    const __half* wl = g_wbT_lo + (size_t)s * KCH;

    float4 pre[8];
    g1_loadx(pre, xb, 0, tid);
    g1_loadb(sb, 0, wh, wl, 0, tid); CP_COMMIT;
    g1_conva(smem, 0, pre, tid);
    g1_loadx(pre, xb, 1, tid);
    CP_WAIT(0);
    __syncthreads();

    for (int t = 0; t < NITER; t++) {
        const int cur = t & 1, nxt = cur ^ 1;
        if (t + 1 < NITER) { g1_loadb(sb, nxt, wh, wl, t + 1, tid); CP_COMMIT; }
        g1_compute(sb, cur, acc, m0, n0, lane);
        if (t + 1 < NITER) {
            g1_conva(smem, nxt, pre, tid);
            if (t + 2 < NITER) g1_loadx(pre, xb, t + 2, tid);
            CP_WAIT(0);
        }
        __syncthreads();
    }

    const int gid = lane >> 2, tg = lane & 3;
    float* dst = g_part + (size_t)(s * BB + b) * CI * KM;
    #pragma unroll
    for (int mi = 0; mi < 4; mi++)
        #pragma unroll
        for (int ni = 0; ni < 4; ni++) {
            int row = m0 + mi * 16 + gid;
            int col = n0 + ni * 8 + tg * 2;
            *(float2*)(dst + (size_t)row * KM + col) =
                make_float2(acc[mi][ni][0], acc[mi][ni][1]);
            *(float2*)(dst + (size_t)(row + 8) * KM + col) =
                make_float2(acc[mi][ni][2], acc[mi][ni][3]);
        }
}

// ---------------------------------------------------------------------------
// Deterministic split-K reduction (float4)
// ---------------------------------------------------------------------------
__global__ __launch_bounds__(256) void reduce_kernel() {
    int idx = (blockIdx.x * 256 + threadIdx.x) * 4;
    float4 s = make_float4(0.f, 0.f, 0.f, 0.f);
    #pragma unroll
    for (int p = 0; p < NSPLIT; p++) {
        float4 v = *(const float4*)(g_part + (size_t)p * (BB * CI * KM) + idx);
        s.x += v.x; s.y += v.y; s.z += v.z; s.w += v.w;
    }
    *(float4*)(g_xco + idx) = s;
}

// ---------------------------------------------------------------------------
// mix: x_hat[b,o,k] = sum_i x_co[b,i,k] * W[i,o,k]; emit fp16 hi/lo (exact pair)
// ---------------------------------------------------------------------------
__global__ __launch_bounds__(128) void mix_kernel(const float* __restrict__ W) {
    const int o0 = blockIdx.x * 4, b0 = blockIdx.y * 4;   // grid (32, 4)
    const int k = threadIdx.x;
    float acc[4][4];
    #pragma unroll
    for (int oo = 0; oo < 4; oo++)
        #pragma unroll
        for (int bb = 0; bb < 4; bb++) acc[oo][bb] = 0.0f;

    for (int i = 0; i < CI; i++) {
        float wv[4], xv[4];
        #pragma unroll
        for (int oo = 0; oo < 4; oo++)
            wv[oo] = W[((size_t)i * CO + o0 + oo) * KM + k];
        #pragma unroll
        for (int bb = 0; bb < 4; bb++)
            xv[bb] = g_xco[((size_t)(b0 + bb) * CI + i) * KM + k];
        #pragma unroll
        for (int oo = 0; oo < 4; oo++)
            #pragma unroll
            for (int bb = 0; bb < 4; bb++)
                acc[oo][bb] = fmaf(xv[bb], wv[oo], acc[oo][bb]);
    }
    #pragma unroll
    for (int oo = 0; oo < 4; oo++)
        #pragma unroll
        for (int bb = 0; bb < 4; bb++) {
            __half h, l; split2h(acc[oo][bb], h, l);
            size_t idx = ((size_t)(b0 + bb) * CO + o0 + oo) * KM + k;
            g_xhat_hi[idx] = h;
            g_xhat_lo[idx] = l;
        }
}

// ---------------------------------------------------------------------------
// GEMM3: out[b, o, :] = x_hat[b] @ bases^T.  Grid (32, 16): each CTA loads
//   A (x_hat hi/lo, 64KB) once + ALL 4 jobs' B tiles upfront via cp.async.
//   smem: Ah@0 Al@32K, B[j]@64K + j*32K.  Total 192KB.  No buffer reuse.
// ---------------------------------------------------------------------------
#define G3_AL 32768
#define G3_B0 65536
#define G3_BST 32768
#define G3_SMEM (G3_B0 + 4 * G3_BST)   // 196608

__global__ __launch_bounds__(256, 1) void gemm3_kernel(float* __restrict__ out) {
    extern __shared__ __align__(128) char smem[];
    const uint32_t sb = smem_u32(smem);
    const int bx = blockIdx.x, b = blockIdx.y;
    const int tid = threadIdx.x, wid = tid >> 5, lane = tid & 31;
    const int m0 = (wid >> 2) * 64, n0 = (wid & 3) * 32;

    // A: x_hat hi/lo [128 o x 128 k], 256B rows, swizzled  (group 0, with B0)
    const __half* xh = g_xhat_hi + (size_t)b * CO * KM;
    const __half* xl = g_xhat_lo + (size_t)b * CO * KM;
    #pragma unroll
    for (int i = 0; i < 8; i++) {
        int e = tid + i * 256;
        int r = e >> 4, g = e & 15;
        uint32_t off = SWZ256((uint32_t)(r * 256 + g * 16));
        CP16(sb + off,         xh + (size_t)r * KM + g * 8);
        CP16(sb + G3_AL + off, xl + (size_t)r * KM + g * 8);
    }
    // B jobs 0..3, one commit group each (group j covers B[j]; group 0 also A)
    #pragma unroll
    for (int j = 0; j < 4; j++) {
        const int x0 = (bx * 4 + j) * 128;
        uint32_t base = sb + G3_B0 + j * G3_BST;
        #pragma unroll
        for (int i = 0; i < 8; i++) {
            int e = tid + i * 256;
            int r = e >> 4, g = e & 15;
            uint32_t off = SWZ256((uint32_t)(r * 256 + g * 16));
            CP16(base + off, g_ba + (size_t)(x0 + r) * KM + g * 8);
        }
        CP_COMMIT;
    }

    const int a_row = lane & 15, a_kh = lane >> 4;
    const int b_row = lane & 7,  b_kh = (lane >> 3) & 1;
    const int gid = lane >> 2, tg = lane & 3;

    for (int j = 0; j < 4; j++) {
        switch (j) {
            case 0: CP_WAIT(3); break;
            case 1: CP_WAIT(2); break;
            case 2: CP_WAIT(1); break;
            default: CP_WAIT(0); break;
        }
        __syncthreads();

        const uint32_t bbase = sb + G3_B0 + j * G3_BST;
        float acc[4][4][4];
        #pragma unroll
        for (int mi = 0; mi < 4; mi++)
            #pragma unroll
            for (int ni = 0; ni < 4; ni++)
                #pragma unroll
                for (int q = 0; q < 4; q++) acc[mi][ni][q] = 0.0f;

        #pragma unroll
        for (int ks = 0; ks < 8; ks++) {
            uint32_t ah[4][4], al[4][4], bv[4][2];
            #pragma unroll
            for (int mi = 0; mi < 4; mi++) {
                uint32_t off = SWZ256((uint32_t)((m0 + mi * 16 + a_row) * 256 + ks * 32 + a_kh * 16));
                LDSM_X4(ah[mi][0], ah[mi][1], ah[mi][2], ah[mi][3], sb + off);
                LDSM_X4(al[mi][0], al[mi][1], al[mi][2], al[mi][3], sb + G3_AL + off);
            }
            #pragma unroll
            for (int ni = 0; ni < 4; ni++) {
                uint32_t off = SWZ256((uint32_t)((n0 + ni * 8 + b_row) * 256 + ks * 32 + b_kh * 16));
                LDSM_X2(bv[ni][0], bv[ni][1], bbase + off);
            }
            #pragma unroll
            for (int mi = 0; mi < 4; mi++)
                #pragma unroll
                for (int ni = 0; ni < 4; ni++) mma16816h(acc[mi][ni], ah[mi], bv[ni]);
            #pragma unroll
            for (int mi = 0; mi < 4; mi++)
                #pragma unroll
                for (int ni = 0; ni < 4; ni++) mma16816h(acc[mi][ni], al[mi], bv[ni]);
        }

        const int x0 = (bx * 4 + j) * 128;
        float* ob = out + (size_t)b * CO * NPTS + x0;
        #pragma unroll
        for (int mi = 0; mi < 4; mi++)
            #pragma unroll
            for (int ni = 0; ni < 4; ni++) {
                int row = m0 + mi * 16 + gid;
                int col = n0 + ni * 8 + tg * 2;
                *(float2*)(ob + (size_t)row * NPTS + col) =
                    make_float2(acc[mi][ni][0], acc[mi][ni][1]);
                *(float2*)(ob + (size_t)(row + 8) * NPTS + col) =
                    make_float2(acc[mi][ni][2], acc[mi][ni][3]);
            }
    }
}

// ---------------------------------------------------------------------------
extern "C" void kernel_launch(void* const* d_in, const int* in_sizes, int n_in,
                              void* d_out, int out_size) {
    const float* x  = (const float*)d_in[0];   // [16,128,16384]
    const float* wb = (const float*)d_in[1];   // wbases [16384,128]
    const float* ba = (const float*)d_in[2];   // bases  [16384,128]
    const float* W  = (const float*)d_in[3];   // [128,128,128]
    float* out = (float*)d_out;                // [16,128,16384]

    cudaFuncSetAttribute(gemm1_kernel, cudaFuncAttributeMaxDynamicSharedMemorySize, G1_SMEM);
    cudaFuncSetAttribute(gemm3_kernel, cudaFuncAttributeMaxDynamicSharedMemorySize, G3_SMEM);

    prep_wb<<<dim3(NPTS / 32, KM / 32), dim3(32, 8)>>>(wb);
    prep_ba<<<(NPTS * KM) / 1024, 256>>>(ba);
    gemm1_kernel<<<dim3(NSPLIT, BB), 256, G1_SMEM>>>(x);
    reduce_kernel<<<(BB * CI * KM) / 1024, 256>>>();
    mix_kernel<<<dim3(CO / 4, BB / 4), 128>>>(W);
    gemm3_kernel<<<dim3(NPTS / 512, BB), 256, G3_SMEM>>>(out);
}

// round 12
// speedup vs baseline: 2.7383x; 1.6509x over previous
#include <cuda_runtime.h>
#include <cuda_fp16.h>
#include <cstdint>

// GalerkinConv via mma.sync fp16 single-limb GEMMs (sm_103 baseline ISA)
// B=16, C_IN=128, C_OUT=128, N=16384, MODES=128
#define BB 16
#define CI 128
#define CO 128
#define NPTS 16384
#define KM 128
#define NSPLIT 16
#define KCH (NPTS / NSPLIT)   // 1024 n per GEMM1 CTA
#define KBLK 64
#define NITER (KCH / KBLK)    // 16

// ---------------- scratch (static device globals; no allocation) ----------
__device__ float  g_part[NSPLIT * BB * CI * KM];   // 16.8 MB
__device__ float  g_xco [BB * CI * KM];
__device__ __half g_xhat[BB * CO * KM];            // x_hat fp16, [b][o][k]
__device__ __half g_wbT [KM * NPTS];               // wbases^T fp16, [mode][n]
__device__ __half g_ba  [NPTS * KM];               // bases fp16, [n][k]

// ---------------- helpers --------------------------------------------------
__device__ __forceinline__ uint32_t smem_u32(const void* p) {
    uint32_t a;
    asm("{ .reg .u64 t; cvta.to.shared.u64 t, %1; cvt.u32.u64 %0, t; }"
        : "=r"(a) : "l"(p));
    return a;
}

#define SWZ128(o) ((o) ^ (((o) >> 3) & 0x70))   // 128B rows
#define SWZ256(o) ((o) ^ (((o) >> 4) & 0x70))   // 256B rows

#define LDSM_X4(r0, r1, r2, r3, a) \
    asm volatile("ldmatrix.sync.aligned.m8n8.x4.shared.b16 {%0,%1,%2,%3}, [%4];" \
                 : "=r"(r0), "=r"(r1), "=r"(r2), "=r"(r3) : "r"(a))
#define LDSM_X2(r0, r1, a) \
    asm volatile("ldmatrix.sync.aligned.m8n8.x2.shared.b16 {%0,%1}, [%2];" \
                 : "=r"(r0), "=r"(r1) : "r"(a))

#define CP16(dst_u32, src_ptr) \
    asm volatile("cp.async.cg.shared.global [%0], [%1], 16;" \
                 :: "r"(dst_u32), "l"(src_ptr))
#define CP_COMMIT asm volatile("cp.async.commit_group;" ::: "memory")
#define CP_WAIT(n) asm volatile("cp.async.wait_group %0;" :: "n"(n) : "memory")

__device__ __forceinline__ void mma16816h(float* d, const uint32_t* a, const uint32_t* b) {
    asm volatile(
        "mma.sync.aligned.m16n8k16.row.col.f32.f16.f16.f32 "
        "{%0,%1,%2,%3}, {%4,%5,%6,%7}, {%8,%9}, {%0,%1,%2,%3};"
        : "+f"(d[0]), "+f"(d[1]), "+f"(d[2]), "+f"(d[3])
        : "r"(a[0]), "r"(a[1]), "r"(a[2]), "r"(a[3]), "r"(b[0]), "r"(b[1]));
}

__device__ __forceinline__ uint32_t pack2h(__half a, __half b) {
    return (uint32_t)__half_as_ushort(a) | ((uint32_t)__half_as_ushort(b) << 16);
}

// ---------------------------------------------------------------------------
// preps
// ---------------------------------------------------------------------------
__global__ void prep_wb(const float* __restrict__ wb) {
    __shared__ float t[32][33];
    const int n0 = blockIdx.x * 32, k0 = blockIdx.y * 32;
    const int tx = threadIdx.x, ty = threadIdx.y;   // (32, 8)
    #pragma unroll
    for (int i = 0; i < 4; i++)
        t[ty + i * 8][tx] = wb[(size_t)(n0 + ty + i * 8) * KM + k0 + tx];
    __syncthreads();
    #pragma unroll
    for (int i = 0; i < 4; i++) {
        float v = t[tx][ty + i * 8];
        g_wbT[(size_t)(k0 + ty + i * 8) * NPTS + n0 + tx] = __float2half(v);
    }
}

__global__ void prep_ba(const float* __restrict__ ba) {
    int i = (blockIdx.x * 256 + threadIdx.x) * 4;
    float4 v = *(const float4*)(ba + i);
    *(uint2*)(g_ba + i) = make_uint2(
        pack2h(__float2half(v.x), __float2half(v.y)),
        pack2h(__float2half(v.z), __float2half(v.w)));
}

// ---------------------------------------------------------------------------
// GEMM1: partial[s][b] = x[b,:,chunk] @ wbases-chunk
//   M=128(c) x N=128(modes) x K=1024 in 16 blocks of 64, double-buffered.
//   Single fp16 limbs.  Stage 32KB: A@0 B@16K.
// ---------------------------------------------------------------------------
#define G1_STAGE 32768
#define G1_SMEM (2 * G1_STAGE)

__device__ __forceinline__ void g1_loadx(float4* pre, const float* xb, int t, int tid) {
    #pragma unroll
    for (int i = 0; i < 8; i++) {
        int e = tid + i * 256;
        int c = e >> 4, q = e & 15;
        pre[i] = *(const float4*)(xb + (size_t)c * NPTS + t * KBLK + q * 4);
    }
}
__device__ __forceinline__ void g1_conva(char* smem, int st, const float4* pre, int tid) {
    char* base = smem + st * G1_STAGE;
    #pragma unroll
    for (int i = 0; i < 8; i++) {
        int e = tid + i * 256;
        int c = e >> 4, q = e & 15;
        uint32_t off = SWZ128((uint32_t)(c * 128 + q * 8));
        *(uint2*)(base + off) = make_uint2(
            pack2h(__float2half(pre[i].x), __float2half(pre[i].y)),
            pack2h(__float2half(pre[i].z), __float2half(pre[i].w)));
    }
}
__device__ __forceinline__ void g1_loadb(uint32_t sb, int st, const __half* w,
                                         int t, int tid) {
    uint32_t base = sb + st * G1_STAGE + 16384;
    #pragma unroll
    for (int i = 0; i < 4; i++) {
        int e = tid + i * 256;
        int r = e >> 3, g = e & 7;
        uint32_t off = SWZ128((uint32_t)(r * 128 + g * 16));
        CP16(base + off, w + (size_t)r * NPTS + t * KBLK + g * 8);
    }
}
__device__ __forceinline__ void g1_compute(uint32_t sb, int st, float acc[4][4][4],
                                           int m0, int n0, int lane) {
    const uint32_t base = sb + st * G1_STAGE;
    const int a_row = lane & 15, a_kh = lane >> 4;
    const int b_row = lane & 7,  b_kh = (lane >> 3) & 1;
    #pragma unroll
    for (int ks = 0; ks < 4; ks++) {
        uint32_t bv[4][2], a[4][4];
        #pragma unroll
        for (int ni = 0; ni < 4; ni++) {
            uint32_t off = SWZ128((uint32_t)((n0 + ni * 8 + b_row) * 128 + ks * 32 + b_kh * 16));
            LDSM_X2(bv[ni][0], bv[ni][1], base + 16384 + off);
        }
        #pragma unroll
        for (int mi = 0; mi < 4; mi++) {
            uint32_t off = SWZ128((uint32_t)((m0 + mi * 16 + a_row) * 128 + ks * 32 + a_kh * 16));
            LDSM_X4(a[mi][0], a[mi][1], a[mi][2], a[mi][3], base + off);
        }
        #pragma unroll
        for (int mi = 0; mi < 4; mi++)
            #pragma unroll
            for (int ni = 0; ni < 4; ni++) mma16816h(acc[mi][ni], a[mi], bv[ni]);
    }
}

__global__ __launch_bounds__(256, 1) void gemm1_kernel(const float* __restrict__ x) {
    extern __shared__ __align__(128) char smem[];
    const uint32_t sb = smem_u32(smem);
    const int s = blockIdx.x, b = blockIdx.y;
    const int tid = threadIdx.x, wid = tid >> 5, lane = tid & 31;
    const int m0 = (wid >> 2) * 64, n0 = (wid & 3) * 32;

    float acc[4][4][4];
    #pragma unroll
    for (int mi = 0; mi < 4; mi++)
        #pragma unroll
        for (int ni = 0; ni < 4; ni++)
            #pragma unroll
            for (int j = 0; j < 4; j++) acc[mi][ni][j] = 0.0f;

    const float* xb = x + (size_t)b * CI * NPTS + (size_t)s * KCH;
    const __half* w = g_wbT + (size_t)s * KCH;

    float4 pre[8];
    g1_loadx(pre, xb, 0, tid);
    g1_loadb(sb, 0, w, 0, tid); CP_COMMIT;
    g1_conva(smem, 0, pre, tid);
    g1_loadx(pre, xb, 1, tid);
    CP_WAIT(0);
    __syncthreads();

    for (int t = 0; t < NITER; t++) {
        const int cur = t & 1, nxt = cur ^ 1;
        if (t + 1 < NITER) { g1_loadb(sb, nxt, w, t + 1, tid); CP_COMMIT; }
        g1_compute(sb, cur, acc, m0, n0, lane);
        if (t + 1 < NITER) {
            g1_conva(smem, nxt, pre, tid);
            if (t + 2 < NITER) g1_loadx(pre, xb, t + 2, tid);
            CP_WAIT(0);
        }
        __syncthreads();
    }

    const int gid = lane >> 2, tg = lane & 3;
    float* dst = g_part + (size_t)(s * BB + b) * CI * KM;
    #pragma unroll
    for (int mi = 0; mi < 4; mi++)
        #pragma unroll
        for (int ni = 0; ni < 4; ni++) {
            int row = m0 + mi * 16 + gid;
            int col = n0 + ni * 8 + tg * 2;
            *(float2*)(dst + (size_t)row * KM + col) =
                make_float2(acc[mi][ni][0], acc[mi][ni][1]);
            *(float2*)(dst + (size_t)(row + 8) * KM + col) =
                make_float2(acc[mi][ni][2], acc[mi][ni][3]);
        }
}

// ---------------------------------------------------------------------------
// Deterministic split-K reduction (float4)
// ---------------------------------------------------------------------------
__global__ __launch_bounds__(256) void reduce_kernel() {
    int idx = (blockIdx.x * 256 + threadIdx.x) * 4;
    float4 s = make_float4(0.f, 0.f, 0.f, 0.f);
    #pragma unroll
    for (int p = 0; p < NSPLIT; p++) {
        float4 v = *(const float4*)(g_part + (size_t)p * (BB * CI * KM) + idx);
        s.x += v.x; s.y += v.y; s.z += v.z; s.w += v.w;
    }
    *(float4*)(g_xco + idx) = s;
}

// ---------------------------------------------------------------------------
// mix: x_hat[b,o,k] = sum_i x_co[b,i,k] * W[i,o,k]; emit single fp16
// ---------------------------------------------------------------------------
__global__ __launch_bounds__(128) void mix_kernel(const float* __restrict__ W) {
    const int o0 = blockIdx.x * 4, b0 = blockIdx.y * 4;   // grid (32, 4)
    const int k = threadIdx.x;
    float acc[4][4];
    #pragma unroll
    for (int oo = 0; oo < 4; oo++)
        #pragma unroll
        for (int bb = 0; bb < 4; bb++) acc[oo][bb] = 0.0f;

    for (int i = 0; i < CI; i++) {
        float wv[4], xv[4];
        #pragma unroll
        for (int oo = 0; oo < 4; oo++)
            wv[oo] = W[((size_t)i * CO + o0 + oo) * KM + k];
        #pragma unroll
        for (int bb = 0; bb < 4; bb++)
            xv[bb] = g_xco[((size_t)(b0 + bb) * CI + i) * KM + k];
        #pragma unroll
        for (int oo = 0; oo < 4; oo++)
            #pragma unroll
            for (int bb = 0; bb < 4; bb++)
                acc[oo][bb] = fmaf(xv[bb], wv[oo], acc[oo][bb]);
    }
    #pragma unroll
    for (int oo = 0; oo < 4; oo++)
        #pragma unroll
        for (int bb = 0; bb < 4; bb++)
            g_xhat[((size_t)(b0 + bb) * CO + o0 + oo) * KM + k] =
                __float2half(acc[oo][bb]);
}

// ---------------------------------------------------------------------------
// GEMM3: out[b, o, :] = x_hat[b] @ bases^T.  Grid (32, 16): each CTA loads
//   A (x_hat, 32KB) once + ALL 4 jobs' B tiles upfront via cp.async.
//   smem: A@0, B[j]@32K + j*32K.  Total 160KB.
// ---------------------------------------------------------------------------
#define G3_B0 32768
#define G3_BST 32768
#define G3_SMEM (G3_B0 + 4 * G3_BST)   // 163840

__global__ __launch_bounds__(256, 1) void gemm3_kernel(float* __restrict__ out) {
    extern __shared__ __align__(128) char smem[];
    const uint32_t sb = smem_u32(smem);
    const int bx = blockIdx.x, b = blockIdx.y;
    const int tid = threadIdx.x, wid = tid >> 5, lane = tid & 31;
    const int m0 = (wid >> 2) * 64, n0 = (wid & 3) * 32;

    // A: x_hat [128 o x 128 k], 256B rows, swizzled (goes with group 0)
    const __half* xh = g_xhat + (size_t)b * CO * KM;
    #pragma unroll
    for (int i = 0; i < 8; i++) {
        int e = tid + i * 256;
        int r = e >> 4, g = e & 15;
        uint32_t off = SWZ256((uint32_t)(r * 256 + g * 16));
        CP16(sb + off, xh + (size_t)r * KM + g * 8);
    }
    // B jobs 0..3, one commit group each
    #pragma unroll
    for (int j = 0; j < 4; j++) {
        const int x0 = (bx * 4 + j) * 128;
        uint32_t base = sb + G3_B0 + j * G3_BST;
        #pragma unroll
        for (int i = 0; i < 8; i++) {
            int e = tid + i * 256;
            int r = e >> 4, g = e & 15;
            uint32_t off = SWZ256((uint32_t)(r * 256 + g * 16));
            CP16(base + off, g_ba + (size_t)(x0 + r) * KM + g * 8);
        }
        CP_COMMIT;
    }

    const int a_row = lane & 15, a_kh = lane >> 4;
    const int b_row = lane & 7,  b_kh = (lane >> 3) & 1;
    const int gid = lane >> 2, tg = lane & 3;

    for (int j = 0; j < 4; j++) {
        switch (j) {
            case 0: CP_WAIT(3); break;
            case 1: CP_WAIT(2); break;
            case 2: CP_WAIT(1); break;
            default: CP_WAIT(0); break;
        }
        __syncthreads();

        const uint32_t bbase = sb + G3_B0 + j * G3_BST;
        float acc[4][4][4];
        #pragma unroll
        for (int mi = 0; mi < 4; mi++)
            #pragma unroll
            for (int ni = 0; ni < 4; ni++)
                #pragma unroll
                for (int q = 0; q < 4; q++) acc[mi][ni][q] = 0.0f;

        #pragma unroll
        for (int ks = 0; ks < 8; ks++) {
            uint32_t a[4][4], bv[4][2];
            #pragma unroll
            for (int mi = 0; mi < 4; mi++) {
                uint32_t off = SWZ256((uint32_t)((m0 + mi * 16 + a_row) * 256 + ks * 32 + a_kh * 16));
                LDSM_X4(a[mi][0], a[mi][1], a[mi][2], a[mi][3], sb + off);
            }
            #pragma unroll
            for (int ni = 0; ni < 4; ni++) {
                uint32_t off = SWZ256((uint32_t)((n0 + ni * 8 + b_row) * 256 + ks * 32 + b_kh * 16));
                LDSM_X2(bv[ni][0], bv[ni][1], bbase + off);
            }
            #pragma unroll
            for (int mi = 0; mi < 4; mi++)
                #pragma unroll
                for (int ni = 0; ni < 4; ni++) mma16816h(acc[mi][ni], a[mi], bv[ni]);
        }

        const int x0 = (bx * 4 + j) * 128;
        float* ob = out + (size_t)b * CO * NPTS + x0;
        #pragma unroll
        for (int mi = 0; mi < 4; mi++)
            #pragma unroll
            for (int ni = 0; ni < 4; ni++) {
                int row = m0 + mi * 16 + gid;
                int col = n0 + ni * 8 + tg * 2;
                *(float2*)(ob + (size_t)row * NPTS + col) =
                    make_float2(acc[mi][ni][0], acc[mi][ni][1]);
                *(float2*)(ob + (size_t)(row + 8) * NPTS + col) =
                    make_float2(acc[mi][ni][2], acc[mi][ni][3]);
            }
    }
}

// ---------------------------------------------------------------------------
extern "C" void kernel_launch(void* const* d_in, const int* in_sizes, int n_in,
                              void* d_out, int out_size) {
    const float* x  = (const float*)d_in[0];   // [16,128,16384]
    const float* wb = (const float*)d_in[1];   // wbases [16384,128]
    const float* ba = (const float*)d_in[2];   // bases  [16384,128]
    const float* W  = (const float*)d_in[3];   // [128,128,128]
    float* out = (float*)d_out;                // [16,128,16384]

    cudaFuncSetAttribute(gemm1_kernel, cudaFuncAttributeMaxDynamicSharedMemorySize, G1_SMEM);
    cudaFuncSetAttribute(gemm3_kernel, cudaFuncAttributeMaxDynamicSharedMemorySize, G3_SMEM);

    prep_wb<<<dim3(NPTS / 32, KM / 32), dim3(32, 8)>>>(wb);
    prep_ba<<<(NPTS * KM) / 1024, 256>>>(ba);
    gemm1_kernel<<<dim3(NSPLIT, BB), 256, G1_SMEM>>>(x);
    reduce_kernel<<<(BB * CI * KM) / 1024, 256>>>();
    mix_kernel<<<dim3(CO / 4, BB / 4), 128>>>(W);
    gemm3_kernel<<<dim3(NPTS / 512, BB), 256, G3_SMEM>>>(out);
}

// round 14
// speedup vs baseline: 3.4132x; 1.2464x over previous
#include <cuda_runtime.h>
#include <cuda_fp16.h>
#include <cstdint>

// GalerkinConv via mma.sync fp16 single-limb GEMMs (sm_103 baseline ISA)
// B=16, C_IN=128, C_OUT=128, N=16384, MODES=128
#define BB 16
#define CI 128
#define CO 128
#define NPTS 16384
#define KM 128
#define NSPLIT 16
#define KCH (NPTS / NSPLIT)   // 1024 n per GEMM1 CTA
#define KBLK 64
#define NITER (KCH / KBLK)    // 16

// ---------------- scratch (static device globals; no allocation) ----------
__device__ float  g_part[NSPLIT * BB * CI * KM];   // 16.8 MB
__device__ float  g_xco [BB * CI * KM];
__device__ __half g_xhat[BB * CO * KM];            // x_hat fp16, [b][o][k]
__device__ __half g_wbT [KM * NPTS];               // wbases^T fp16, [mode][n]
__device__ __half g_ba  [NPTS * KM];               // bases fp16, [n][k]

// ---------------- helpers --------------------------------------------------
__device__ __forceinline__ uint32_t smem_u32(const void* p) {
    uint32_t a;
    asm("{ .reg .u64 t; cvta.to.shared.u64 t, %1; cvt.u32.u64 %0, t; }"
        : "=r"(a) : "l"(p));
    return a;
}

#define SWZ128(o) ((o) ^ (((o) >> 3) & 0x70))   // 128B rows
#define SWZ256(o) ((o) ^ (((o) >> 4) & 0x70))   // 256B rows

#define LDSM_X4(r0, r1, r2, r3, a) \
    asm volatile("ldmatrix.sync.aligned.m8n8.x4.shared.b16 {%0,%1,%2,%3}, [%4];" \
                 : "=r"(r0), "=r"(r1), "=r"(r2), "=r"(r3) : "r"(a))
#define LDSM_X2(r0, r1, a) \
    asm volatile("ldmatrix.sync.aligned.m8n8.x2.shared.b16 {%0,%1}, [%2];" \
                 : "=r"(r0), "=r"(r1) : "r"(a))

#define CP16(dst_u32, src_ptr) \
    asm volatile("cp.async.cg.shared.global [%0], [%1], 16;" \
                 :: "r"(dst_u32), "l"(src_ptr))
#define CP_COMMIT asm volatile("cp.async.commit_group;" ::: "memory")
#define CP_WAIT(n) asm volatile("cp.async.wait_group %0;" :: "n"(n) : "memory")

__device__ __forceinline__ void mma16816h(float* d, const uint32_t* a, const uint32_t* b) {
    asm volatile(
        "mma.sync.aligned.m16n8k16.row.col.f32.f16.f16.f32 "
        "{%0,%1,%2,%3}, {%4,%5,%6,%7}, {%8,%9}, {%0,%1,%2,%3};"
        : "+f"(d[0]), "+f"(d[1]), "+f"(d[2]), "+f"(d[3])
        : "r"(a[0]), "r"(a[1]), "r"(a[2]), "r"(a[3]), "r"(b[0]), "r"(b[1]));
}

__device__ __forceinline__ uint32_t pack2h(__half a, __half b) {
    return (uint32_t)__half_as_ushort(a) | ((uint32_t)__half_as_ushort(b) << 16);
}

// ---------------------------------------------------------------------------
// preps
// ---------------------------------------------------------------------------
__global__ void prep_wb(const float* __restrict__ wb) {
    __shared__ float t[32][33];
    const int n0 = blockIdx.x * 32, k0 = blockIdx.y * 32;
    const int tx = threadIdx.x, ty = threadIdx.y;   // (32, 8)
    #pragma unroll
    for (int i = 0; i < 4; i++)
        t[ty + i * 8][tx] = wb[(size_t)(n0 + ty + i * 8) * KM + k0 + tx];
    __syncthreads();
    #pragma unroll
    for (int i = 0; i < 4; i++) {
        float v = t[tx][ty + i * 8];
        g_wbT[(size_t)(k0 + ty + i * 8) * NPTS + n0 + tx] = __float2half(v);
    }
}

__global__ void prep_ba(const float* __restrict__ ba) {
    int i = (blockIdx.x * 256 + threadIdx.x) * 4;
    float4 v = *(const float4*)(ba + i);
    *(uint2*)(g_ba + i) = make_uint2(
        pack2h(__float2half(v.x), __float2half(v.y)),
        pack2h(__float2half(v.z), __float2half(v.w)));
}

// ---------------------------------------------------------------------------
// GEMM1: partial[s][b] = x[b,:,chunk] @ wbases-chunk
//   M=128(c) x N=128(modes) x K=1024 in 16 blocks of 64, double-buffered.
//   Stage 32KB: A@0 B@16K.  2 CTAs/SM (regs<=128): co-CTA hides LDG latency.
// ---------------------------------------------------------------------------
#define G1_STAGE 32768
#define G1_SMEM (2 * G1_STAGE)

// load f32 x tile from global, convert to fp16, store swizzled into A[st]
__device__ __forceinline__ void g1_conva(char* smem, int st, const float* xb,
                                         int t, int tid) {
    char* base = smem + st * G1_STAGE;
    #pragma unroll
    for (int i = 0; i < 8; i++) {
        int e = tid + i * 256;            // 0..2047 granules
        int c = e >> 4, q = e & 15;
        float4 v = *(const float4*)(xb + (size_t)c * NPTS + t * KBLK + q * 4);
        uint32_t off = SWZ128((uint32_t)(c * 128 + q * 8));
        *(uint2*)(base + off) = make_uint2(
            pack2h(__float2half(v.x), __float2half(v.y)),
            pack2h(__float2half(v.z), __float2half(v.w)));
    }
}
__device__ __forceinline__ void g1_loadb(uint32_t sb, int st, const __half* w,
                                         int t, int tid) {
    uint32_t base = sb + st * G1_STAGE + 16384;
    #pragma unroll
    for (int i = 0; i < 4; i++) {
        int e = tid + i * 256;
        int r = e >> 3, g = e & 7;
        uint32_t off = SWZ128((uint32_t)(r * 128 + g * 16));
        CP16(base + off, w + (size_t)r * NPTS + t * KBLK + g * 8);
    }
}
__device__ __forceinline__ void g1_compute(uint32_t sb, int st, float acc[4][4][4],
                                           int m0, int n0, int lane) {
    const uint32_t base = sb + st * G1_STAGE;
    const int a_row = lane & 15, a_kh = lane >> 4;
    const int b_row = lane & 7,  b_kh = (lane >> 3) & 1;
    #pragma unroll
    for (int ks = 0; ks < 4; ks++) {
        uint32_t bv[4][2], a[4][4];
        #pragma unroll
        for (int ni = 0; ni < 4; ni++) {
            uint32_t off = SWZ128((uint32_t)((n0 + ni * 8 + b_row) * 128 + ks * 32 + b_kh * 16));
            LDSM_X2(bv[ni][0], bv[ni][1], base + 16384 + off);
        }
        #pragma unroll
        for (int mi = 0; mi < 4; mi++) {
            uint32_t off = SWZ128((uint32_t)((m0 + mi * 16 + a_row) * 128 + ks * 32 + a_kh * 16));
            LDSM_X4(a[mi][0], a[mi][1], a[mi][2], a[mi][3], base + off);
        }
        #pragma unroll
        for (int mi = 0; mi < 4; mi++)
            #pragma unroll
            for (int ni = 0; ni < 4; ni++) mma16816h(acc[mi][ni], a[mi], bv[ni]);
    }
}

__global__ __launch_bounds__(256, 2) void gemm1_kernel(const float* __restrict__ x) {
    extern __shared__ __align__(128) char smem[];
    const uint32_t sb = smem_u32(smem);
    const int s = blockIdx.x, b = blockIdx.y;
    const int tid = threadIdx.x, wid = tid >> 5, lane = tid & 31;
    const int m0 = (wid >> 2) * 64, n0 = (wid & 3) * 32;

    float acc[4][4][4];
    #pragma unroll
    for (int mi = 0; mi < 4; mi++)
        #pragma unroll
        for (int ni = 0; ni < 4; ni++)
            #pragma unroll
            for (int j = 0; j < 4; j++) acc[mi][ni][j] = 0.0f;

    const float* xb = x + (size_t)b * CI * NPTS + (size_t)s * KCH;
    const __half* w = g_wbT + (size_t)s * KCH;

    g1_loadb(sb, 0, w, 0, tid); CP_COMMIT;
    g1_conva(smem, 0, xb, 0, tid);
    CP_WAIT(0);
    __syncthreads();

    for (int t = 0; t < NITER; t++) {
        const int cur = t & 1, nxt = cur ^ 1;
        if (t + 1 < NITER) { g1_loadb(sb, nxt, w, t + 1, tid); CP_COMMIT; }
        g1_compute(sb, cur, acc, m0, n0, lane);
        if (t + 1 < NITER) {
            g1_conva(smem, nxt, xb, t + 1, tid);
            CP_WAIT(0);
        }
        __syncthreads();
    }

    const int gid = lane >> 2, tg = lane & 3;
    float* dst = g_part + (size_t)(s * BB + b) * CI * KM;
    #pragma unroll
    for (int mi = 0; mi < 4; mi++)
        #pragma unroll
        for (int ni = 0; ni < 4; ni++) {
            int row = m0 + mi * 16 + gid;
            int col = n0 + ni * 8 + tg * 2;
            *(float2*)(dst + (size_t)row * KM + col) =
                make_float2(acc[mi][ni][0], acc[mi][ni][1]);
            *(float2*)(dst + (size_t)(row + 8) * KM + col) =
                make_float2(acc[mi][ni][2], acc[mi][ni][3]);
        }
}

// ---------------------------------------------------------------------------
// Deterministic split-K reduction (float4, 512 blocks)
// ---------------------------------------------------------------------------
__global__ __launch_bounds__(128) void reduce_kernel() {
    int idx = (blockIdx.x * 128 + threadIdx.x) * 4;
    float4 s = make_float4(0.f, 0.f, 0.f, 0.f);
    #pragma unroll
    for (int p = 0; p < NSPLIT; p++) {
        float4 v = *(const float4*)(g_part + (size_t)p * (BB * CI * KM) + idx);
        s.x += v.x; s.y += v.y; s.z += v.z; s.w += v.w;
    }
    *(float4*)(g_xco + idx) = s;
}

// ---------------------------------------------------------------------------
// mix: x_hat[b,o,k] = sum_i x_co[b,i,k] * W[i,o,k]; 2o x 2b tiles, 512 blocks
// ---------------------------------------------------------------------------
__global__ __launch_bounds__(128) void mix_kernel(const float* __restrict__ W) {
    const int o0 = blockIdx.x * 2, b0 = blockIdx.y * 2;   // grid (64, 8)
    const int k = threadIdx.x;
    float acc[2][2] = {{0.f, 0.f}, {0.f, 0.f}};

    for (int i = 0; i < CI; i++) {
        float wv[2], xv[2];
        #pragma unroll
        for (int oo = 0; oo < 2; oo++)
            wv[oo] = W[((size_t)i * CO + o0 + oo) * KM + k];
        #pragma unroll
        for (int bb = 0; bb < 2; bb++)
            xv[bb] = g_xco[((size_t)(b0 + bb) * CI + i) * KM + k];
        #pragma unroll
        for (int oo = 0; oo < 2; oo++)
            #pragma unroll
            for (int bb = 0; bb < 2; bb++)
                acc[oo][bb] = fmaf(xv[bb], wv[oo], acc[oo][bb]);
    }
    #pragma unroll
    for (int oo = 0; oo < 2; oo++)
        #pragma unroll
        for (int bb = 0; bb < 2; bb++)
            g_xhat[((size_t)(b0 + bb) * CO + o0 + oo) * KM + k] =
                __float2half(acc[oo][bb]);
}

// ---------------------------------------------------------------------------
// GEMM3: out[b, o, :] = x_hat[b] @ bases^T.  Grid (64, 16): each CTA loads
//   A (x_hat, 32KB) once + 2 jobs' B tiles via cp.async.
//   smem: A@0, B[j]@32K + j*32K.  Total 96KB -> 2 CTAs/SM.
// ---------------------------------------------------------------------------
#define G3_B0 32768
#define G3_BST 32768
#define G3_SMEM (G3_B0 + 2 * G3_BST)   // 98304

__global__ __launch_bounds__(256, 2) void gemm3_kernel(float* __restrict__ out) {
    extern __shared__ __align__(128) char smem[];
    const uint32_t sb = smem_u32(smem);
    const int bx = blockIdx.x, b = blockIdx.y;
    const int tid = threadIdx.x, wid = tid >> 5, lane = tid & 31;
    const int m0 = (wid >> 2) * 64, n0 = (wid & 3) * 32;

    // A: x_hat [128 o x 128 k], 256B rows, swizzled (group 0, with B0)
    const __half* xh = g_xhat + (size_t)b * CO * KM;
    #pragma unroll
    for (int i = 0; i < 8; i++) {
        int e = tid + i * 256;
        int r = e >> 4, g = e & 15;
        uint32_t off = SWZ256((uint32_t)(r * 256 + g * 16));
        CP16(sb + off, xh + (size_t)r * KM + g * 8);
    }
    // B jobs 0..1, one commit group each
    #pragma unroll
    for (int j = 0; j < 2; j++) {
        const int x0 = (bx * 2 + j) * 128;
        uint32_t base = sb + G3_B0 + j * G3_BST;
        #pragma unroll
        for (int i = 0; i < 8; i++) {
            int e = tid + i * 256;
            int r = e >> 4, g = e & 15;
            uint32_t off = SWZ256((uint32_t)(r * 256 + g * 16));
            CP16(base + off, g_ba + (size_t)(x0 + r) * KM + g * 8);
        }
        CP_COMMIT;
    }

    const int a_row = lane & 15, a_kh = lane >> 4;
    const int b_row = lane & 7,  b_kh = (lane >> 3) & 1;
    const int gid = lane >> 2, tg = lane & 3;

    for (int j = 0; j < 2; j++) {
        if (j == 0) { CP_WAIT(1); } else { CP_WAIT(0); }
        __syncthreads();

        const uint32_t bbase = sb + G3_B0 + j * G3_BST;
        float acc[4][4][4];
        #pragma unroll
        for (int mi = 0; mi < 4; mi++)
            #pragma unroll
            for (int ni = 0; ni < 4; ni++)
                #pragma unroll
                for (int q = 0; q < 4; q++) acc[mi][ni][q] = 0.0f;

        #pragma unroll
        for (int ks = 0; ks < 8; ks++) {
            uint32_t a[4][4], bv[4][2];
            #pragma unroll
            for (int mi = 0; mi < 4; mi++) {
                uint32_t off = SWZ256((uint32_t)((m0 + mi * 16 + a_row) * 256 + ks * 32 + a_kh * 16));
                LDSM_X4(a[mi][0], a[mi][1], a[mi][2], a[mi][3], sb + off);
            }
            #pragma unroll
            for (int ni = 0; ni < 4; ni++) {
                uint32_t off = SWZ256((uint32_t)((n0 + ni * 8 + b_row) * 256 + ks * 32 + b_kh * 16));
                LDSM_X2(bv[ni][0], bv[ni][1], bbase + off);
            }
            #pragma unroll
            for (int mi = 0; mi < 4; mi++)
                #pragma unroll
                for (int ni = 0; ni < 4; ni++) mma16816h(acc[mi][ni], a[mi], bv[ni]);
        }

        const int x0 = (bx * 2 + j) * 128;
        float* ob = out + (size_t)b * CO * NPTS + x0;
        #pragma unroll
        for (int mi = 0; mi < 4; mi++)
            #pragma unroll
            for (int ni = 0; ni < 4; ni++) {
                int row = m0 + mi * 16 + gid;
                int col = n0 + ni * 8 + tg * 2;
                *(float2*)(ob + (size_t)row * NPTS + col) =
                    make_float2(acc[mi][ni][0], acc[mi][ni][1]);
                *(float2*)(ob + (size_t)(row + 8) * NPTS + col) =
                    make_float2(acc[mi][ni][2], acc[mi][ni][3]);
            }
    }
}

// ---------------------------------------------------------------------------
extern "C" void kernel_launch(void* const* d_in, const int* in_sizes, int n_in,
                              void* d_out, int out_size) {
    const float* x  = (const float*)d_in[0];   // [16,128,16384]
    const float* wb = (const float*)d_in[1];   // wbases [16384,128]
    const float* ba = (const float*)d_in[2];   // bases  [16384,128]
    const float* W  = (const float*)d_in[3];   // [128,128,128]
    float* out = (float*)d_out;                // [16,128,16384]

    cudaFuncSetAttribute(gemm1_kernel, cudaFuncAttributeMaxDynamicSharedMemorySize, G1_SMEM);
    cudaFuncSetAttribute(gemm3_kernel, cudaFuncAttributeMaxDynamicSharedMemorySize, G3_SMEM);

    prep_wb<<<dim3(NPTS / 32, KM / 32), dim3(32, 8)>>>(wb);
    prep_ba<<<(NPTS * KM) / 1024, 256>>>(ba);
    gemm1_kernel<<<dim3(NSPLIT, BB), 256, G1_SMEM>>>(x);
    reduce_kernel<<<(BB * CI * KM) / 512, 128>>>();
    mix_kernel<<<dim3(CO / 2, BB / 2), 128>>>(W);
    gemm3_kernel<<<dim3(NPTS / 256, BB), 256, G3_SMEM>>>(out);
}